// round 8
// baseline (speedup 1.0000x reference)
#include <cuda_runtime.h>
#include <math.h>
#include <float.h>
#include <stdint.h>

#define BATCH   2
#define SEQ     2048
#define HID     2048
#define NHEADS  16
#define HD      128

// ---------------- static scratch (no allocations allowed) ----------------
__device__ float g_qkv  [BATCH * SEQ * 3 * HID];       // [B,S,3H]
__device__ float g_Q    [BATCH * NHEADS * SEQ * HD];   // [B,NH,S,D] tf32, d-permuted
__device__ float g_K    [BATCH * NHEADS * SEQ * HD];   // tf32, d-permuted
__device__ float g_V    [BATCH * NHEADS * SEQ * HD];   // tf32, natural d
__device__ float g_ctx  [BATCH * SEQ * HID];           // [B,S,H] (tf32-rounded)
__device__ float g_bias [NHEADS * SEQ];                // bias[h][q-k] * log2(e)
__device__ float g_xr   [BATCH * SEQ * HID];           // tf32-rounded x
__device__ float g_wqkvr[HID * 3 * HID];               // tf32-rounded qkv_w
__device__ float g_dwr  [HID * HID];                   // tf32-rounded dense_w
__device__ float g_cos  [SEQ * 64];                    // RoPE tables
__device__ float g_sin  [SEQ * 64];

// ======================= helpers =======================
__device__ __forceinline__ uint32_t smem_u32(const void* p) {
    uint32_t a;
    asm("{ .reg .u64 t; cvta.to.shared.u64 t, %1; cvt.u32.u64 %0, t; }"
        : "=r"(a) : "l"(p));
    return a;
}
__device__ __forceinline__ uint32_t f2tf32(float x) {
    uint32_t r;
    asm("cvt.rna.tf32.f32 %0, %1;" : "=r"(r) : "f"(x));
    return r;
}
__device__ __forceinline__ void cp16(uint32_t s, const void* g) {
    asm volatile("cp.async.cg.shared.global [%0], [%1], 16;" :: "r"(s), "l"(g));
}
__device__ __forceinline__ void cp4(uint32_t s, const void* g) {
    asm volatile("cp.async.ca.shared.global [%0], [%1], 4;" :: "r"(s), "l"(g));
}
#define CP_COMMIT() asm volatile("cp.async.commit_group;" ::: "memory")
#define CP_WAIT1()  asm volatile("cp.async.wait_group 1;"  ::: "memory")
#define CP_WAIT0()  asm volatile("cp.async.wait_group 0;"  ::: "memory")

__device__ __forceinline__ void mma1688(float* d, const uint32_t* a, const uint32_t* b) {
    asm volatile(
        "mma.sync.aligned.m16n8k8.row.col.f32.tf32.tf32.f32 "
        "{%0,%1,%2,%3}, {%4,%5,%6,%7}, {%8,%9}, {%0,%1,%2,%3};"
        : "+f"(d[0]), "+f"(d[1]), "+f"(d[2]), "+f"(d[3])
        : "r"(a[0]), "r"(a[1]), "r"(a[2]), "r"(a[3]), "r"(b[0]), "r"(b[1]));
}

// ======================= tf32 pre-round (elementwise, float4) =======================
__global__ __launch_bounds__(256) void tf32_round_kernel(
    const float* __restrict__ in, float* __restrict__ out)
{
    int i = blockIdx.x * blockDim.x + threadIdx.x;
    float4 v = ((const float4*)in)[i];
    v.x = __uint_as_float(f2tf32(v.x));
    v.y = __uint_as_float(f2tf32(v.y));
    v.z = __uint_as_float(f2tf32(v.z));
    v.w = __uint_as_float(f2tf32(v.w));
    ((float4*)out)[i] = v;
}

// ======================= RoPE cos/sin table =======================
__global__ __launch_bounds__(256) void rope_table_kernel()
{
    int idx = blockIdx.x * blockDim.x + threadIdx.x;   // SEQ*64
    int s = idx >> 6, d = idx & 63;
    float inv = powf(10000.f, -(float)d * (1.f / 64.f));
    float sn, cs;
    sincosf((float)s * inv, &sn, &cs);
    g_cos[idx] = cs;
    g_sin[idx] = sn;
}

// ======================= tf32 mma.sync GEMM: 128x256 tile, warp 64x64 ==============
#define GBM 128
#define GBN 256
#define GBK 16
#define APITCH 20
#define BPITCH 264
#define A_STG (GBM * APITCH)
#define B_STG (GBK * BPITCH)
#define STG_FLOATS (A_STG + B_STG)
#define GEMM_SMEM (3 * STG_FLOATS * 4)

__global__ __launch_bounds__(256, 1) void gemm_mma(
    const float* __restrict__ A, const float* __restrict__ B,
    float* __restrict__ C, int M, int N, int K)
{
    extern __shared__ float sm[];
    const int tid  = threadIdx.x;
    const int warp = tid >> 5, lane = tid & 31;
    const int wm = (warp >> 2) * 64;
    const int wn = (warp & 3) * 64;
    const int r  = lane >> 2;
    const int q  = lane & 3;
    const int row0 = blockIdx.y * GBM;
    const int col0 = blockIdx.x * GBN;
    const uint32_t sb = smem_u32(sm);
    const int NC = K / GBK;

    float cf[4][8][4];
#pragma unroll
    for (int i = 0; i < 4; i++)
#pragma unroll
        for (int j = 0; j < 8; j++)
#pragma unroll
            for (int t = 0; t < 4; t++) cf[i][j][t] = 0.f;

    const int am  = tid >> 2;
    const int akq = (tid & 3) * 4;
    const int bkr = tid >> 6;
    const int bn4 = (tid & 63) * 4;

    auto load_stage = [&](int c, int s) {
        uint32_t base = sb + (uint32_t)(s * STG_FLOATS) * 4u;
        cp16(base + (uint32_t)((am      ) * APITCH + akq) * 4u,
             A + (size_t)(row0 + am      ) * K + c * GBK + akq);
        cp16(base + (uint32_t)((am + 64 ) * APITCH + akq) * 4u,
             A + (size_t)(row0 + am + 64 ) * K + c * GBK + akq);
        uint32_t bbase = base + (uint32_t)A_STG * 4u;
#pragma unroll
        for (int j = 0; j < 4; j++) {
            cp16(bbase + (uint32_t)((bkr + 4 * j) * BPITCH + bn4) * 4u,
                 B + (size_t)(c * GBK + bkr + 4 * j) * N + col0 + bn4);
        }
        CP_COMMIT();
    };

    load_stage(0, 0);
    load_stage(1, 1);

    int buf = 0;
    for (int c = 0; c < NC; ++c) {
        CP_WAIT1();
        __syncthreads();
        int nc = c + 2;
        if (nc < NC) load_stage(nc, nc % 3); else CP_COMMIT();

        const float* As = sm + buf * STG_FLOATS;
        const float* Bs = As + A_STG;
#pragma unroll
        for (int k8 = 0; k8 < GBK; k8 += 8) {
            uint32_t af[4][4], bf[8][2];
#pragma unroll
            for (int mt = 0; mt < 4; mt++) {
                int row = wm + mt * 16 + r;
                af[mt][0] = __float_as_uint(As[(row    ) * APITCH + k8 + q    ]);
                af[mt][1] = __float_as_uint(As[(row + 8) * APITCH + k8 + q    ]);
                af[mt][2] = __float_as_uint(As[(row    ) * APITCH + k8 + q + 4]);
                af[mt][3] = __float_as_uint(As[(row + 8) * APITCH + k8 + q + 4]);
            }
#pragma unroll
            for (int nt = 0; nt < 8; nt++) {
                int cc = wn + nt * 8 + r;
                bf[nt][0] = __float_as_uint(Bs[(k8 + q    ) * BPITCH + cc]);
                bf[nt][1] = __float_as_uint(Bs[(k8 + q + 4) * BPITCH + cc]);
            }
#pragma unroll
            for (int mt = 0; mt < 4; mt++)
#pragma unroll
                for (int nt = 0; nt < 8; nt++)
                    mma1688(cf[mt][nt], af[mt], bf[nt]);
        }
        buf = (buf + 1) % 3;
    }

#pragma unroll
    for (int mt = 0; mt < 4; mt++) {
        int row = row0 + wm + mt * 16 + r;
#pragma unroll
        for (int nt = 0; nt < 8; nt++) {
            int col = col0 + wn + nt * 8 + 2 * q;
            *(float2*)(C + (size_t)row * N + col) =
                make_float2(cf[mt][nt][0], cf[mt][nt][1]);
            *(float2*)(C + (size_t)(row + 8) * N + col) =
                make_float2(cf[mt][nt][2], cf[mt][nt][3]);
        }
    }
}

// ---------------- RoPE + split + tf32 pre-round + d-permute for Q/K ----------------
// perm within each 8-group: j<4 -> 2j ; j>=4 -> 2(j-4)+1. perm(d+64) = perm(d)+64.
__global__ __launch_bounds__(256) void rope_split_kernel()
{
    int t = blockIdx.x * blockDim.x + threadIdx.x;
    int d = t & 63;
    int h = (t >> 6) & (NHEADS - 1);
    int s = (t >> 10) & (SEQ - 1);
    int b = t >> 21;

    const float* base = g_qkv + ((size_t)(b * SEQ + s)) * (3 * HID) + h * HD;
    float q1 = base[d],            q2 = base[d + 64];
    float k1 = base[HID + d],      k2 = base[HID + d + 64];
    float v1 = base[2 * HID + d],  v2 = base[2 * HID + d + 64];

    float cs = g_cos[s * 64 + d];
    float sn = g_sin[s * 64 + d];

    int j = d & 7, g = d >> 3;
    int p = (j < 4) ? (8 * g + 2 * j) : (8 * g + 2 * (j - 4) + 1);

    size_t o = ((size_t)((b * NHEADS + h) * SEQ + s)) * HD;
    g_Q[o + p]      = __uint_as_float(f2tf32(q1 * cs - q2 * sn));
    g_Q[o + p + 64] = __uint_as_float(f2tf32(q2 * cs + q1 * sn));
    g_K[o + p]      = __uint_as_float(f2tf32(k1 * cs - k2 * sn));
    g_K[o + p + 64] = __uint_as_float(f2tf32(k2 * cs + k1 * sn));
    g_V[o + d]      = __uint_as_float(f2tf32(v1));
    g_V[o + d + 64] = __uint_as_float(f2tf32(v2));
}

// ---------------- relative-position bias table (pre-scaled by log2 e) ----------------
__global__ void bias_kernel(const float* __restrict__ rel)
{
    int idx = blockIdx.x * blockDim.x + threadIdx.x;
    if (idx >= NHEADS * SEQ) return;
    int h = idx >> 11;
    int n = idx & (SEQ - 1);
    int bucket;
    if (n < 16) {
        bucket = n;
    } else {
        float val = logf((float)n * (1.f / 16.f)) / logf(8.f) * 16.f;
        int bi = (int)val + 16;
        bucket = bi < 31 ? bi : 31;
    }
    g_bias[idx] = rel[bucket * NHEADS + h] * 1.4426950408889634f;
}

// ---------------- flash attention, FA2-style tf32 mma ----------------
#define FQ   128
#define FKC  64
#define QP   132
#define VP   136
#define OFF_FK (FQ * QP)
#define OFF_FV (OFF_FK + 2 * FKC * QP)
#define OFF_FB (OFF_FV + 2 * FKC * VP)
#define FLASH_FLOATS (OFF_FB + 2 * 192)
#define FLASH_SMEM (FLASH_FLOATS * 4)

__global__ __launch_bounds__(256, 1) void flash_mma_kernel()
{
    extern __shared__ float sm[];
    float* Qs = sm;

    const int qt = (int)gridDim.x - 1 - (int)blockIdx.x;   // heavy blocks first
    const int h = blockIdx.y, b = blockIdx.z;
    const int tid  = threadIdx.x;
    const int warp = tid >> 5, lane = tid & 31;
    const int r = lane >> 2, q = lane & 3;
    const int wr0 = warp * 16;
    const int rA = wr0 + r, rB = rA + 8;
    const uint32_t sbase = smem_u32(sm);

    const size_t headBase = (size_t)(b * NHEADS + h) * SEQ * HD;
    const float* Qg = g_Q + headBase + (size_t)qt * FQ * HD;
    const float* biasH = g_bias + h * SEQ;

    const float SCL2 = 0.08838834764831845f * 1.4426950408889634f;

    // prolog: Q (group0), then KV tile 0 + bias0 (group1)
#pragma unroll
    for (int i = 0; i < 16; i++) {
        int f = tid + i * 256; int rr = f >> 5, c4 = (f & 31) * 4;
        cp16(sbase + (uint32_t)(rr * QP + c4) * 4u, Qg + rr * HD + c4);
    }
    CP_COMMIT();
    {
        const float* Kg = g_K + headBase;
        const float* Vg = g_V + headBase;
#pragma unroll
        for (int i = 0; i < 8; i++) {
            int f = tid + i * 256; int rr = f >> 5, c4 = (f & 31) * 4;
            cp16(sbase + (uint32_t)(OFF_FK + rr * QP + c4) * 4u, Kg + rr * HD + c4);
            cp16(sbase + (uint32_t)(OFF_FV + rr * VP + c4) * 4u, Vg + rr * HD + c4);
        }
        if (tid < 192) {
            int dl = qt * FQ + tid - 63;
            cp4(sbase + (uint32_t)(OFF_FB + tid) * 4u, biasH + (dl >= 0 ? dl : 0));
        }
        CP_COMMIT();
    }
    CP_WAIT1();                        // Q done
    __syncthreads();

    // hoist Q fragments to registers (permuted layout -> float2 loads)
    uint32_t qf[16][4];
#pragma unroll
    for (int k8 = 0; k8 < 16; k8++) {
        float2 a = *(const float2*)&Qs[rA * QP + k8 * 8 + 2 * q];
        float2 bb = *(const float2*)&Qs[rB * QP + k8 * 8 + 2 * q];
        qf[k8][0] = __float_as_uint(a.x);
        qf[k8][1] = __float_as_uint(bb.x);
        qf[k8][2] = __float_as_uint(a.y);
        qf[k8][3] = __float_as_uint(bb.y);
    }

    float m0 = -1e30f, m1 = -1e30f, l0 = 0.f, l1 = 0.f;
    float of[16][4];
#pragma unroll
    for (int nt = 0; nt < 16; nt++)
#pragma unroll
        for (int e = 0; e < 4; e++) of[nt][e] = 0.f;

    const int NT = 2 * qt + 2;

    for (int kt = 0; kt < NT; ++kt) {
        __syncthreads();
        if (kt + 1 < NT) {
            const int ns = (kt + 1) & 1;
            const float* Kg = g_K + headBase + (size_t)(kt + 1) * FKC * HD;
            const float* Vg = g_V + headBase + (size_t)(kt + 1) * FKC * HD;
#pragma unroll
            for (int i = 0; i < 8; i++) {
                int f = tid + i * 256; int rr = f >> 5, c4 = (f & 31) * 4;
                cp16(sbase + (uint32_t)(OFF_FK + ns * FKC * QP + rr * QP + c4) * 4u, Kg + rr * HD + c4);
                cp16(sbase + (uint32_t)(OFF_FV + ns * FKC * VP + rr * VP + c4) * 4u, Vg + rr * HD + c4);
            }
            if (tid < 192) {
                int dl = qt * FQ - (kt + 1) * FKC + tid - 63;
                cp4(sbase + (uint32_t)(OFF_FB + ns * 192 + tid) * 4u,
                    biasH + (dl >= 0 ? dl : 0));
            }
            CP_COMMIT();
            CP_WAIT1();
        } else {
            CP_WAIT0();
        }
        __syncthreads();

        const int base = qt * FQ - kt * FKC;
        if (base < -(wr0 + 15)) continue;       // fully-masked warp

        const float* Kst = sm + OFF_FK + (kt & 1) * FKC * QP;
        const float* Vst = sm + OFF_FV + (kt & 1) * FKC * VP;
        const float* bsm = sm + OFF_FB + (kt & 1) * 192;

        // ---- S = Q K^T (16 x 64 per warp); K permuted -> float2 b-frags
        float s[8][4];
#pragma unroll
        for (int nt = 0; nt < 8; nt++)
#pragma unroll
            for (int e = 0; e < 4; e++) s[nt][e] = 0.f;

#pragma unroll
        for (int k8 = 0; k8 < 16; k8++) {
            int kc = k8 * 8 + 2 * q;
#pragma unroll
            for (int nt = 0; nt < 8; nt++) {
                float2 kv = *(const float2*)&Kst[(nt * 8 + r) * QP + kc];
                uint32_t bf[2];
                bf[0] = __float_as_uint(kv.x);
                bf[1] = __float_as_uint(kv.y);
                mma1688(s[nt], qf[k8], bf);
            }
        }

        // ---- scale + bias (pre-scaled by log2e) + causal mask
        const bool dg = (base < FQ);
#pragma unroll
        for (int nt = 0; nt < 8; nt++) {
            int lc = nt * 8 + 2 * q;
            float v0 = s[nt][0] * SCL2 + bsm[rA - lc + 63];
            float v1 = s[nt][1] * SCL2 + bsm[rA - lc + 62];
            float v2 = s[nt][2] * SCL2 + bsm[rB - lc + 63];
            float v3 = s[nt][3] * SCL2 + bsm[rB - lc + 62];
            s[nt][0] = (dg && lc     > rA + base) ? -1e30f : v0;
            s[nt][1] = (dg && lc + 1 > rA + base) ? -1e30f : v1;
            s[nt][2] = (dg && lc     > rB + base) ? -1e30f : v2;
            s[nt][3] = (dg && lc + 1 > rB + base) ? -1e30f : v3;
        }

        // ---- row max within quad
        float mxA = -1e30f, mxB = -1e30f;
#pragma unroll
        for (int nt = 0; nt < 8; nt++) {
            mxA = fmaxf(mxA, fmaxf(s[nt][0], s[nt][1]));
            mxB = fmaxf(mxB, fmaxf(s[nt][2], s[nt][3]));
        }
        mxA = fmaxf(mxA, __shfl_xor_sync(0xFFFFFFFFu, mxA, 1));
        mxA = fmaxf(mxA, __shfl_xor_sync(0xFFFFFFFFu, mxA, 2));
        mxB = fmaxf(mxB, __shfl_xor_sync(0xFFFFFFFFu, mxB, 1));
        mxB = fmaxf(mxB, __shfl_xor_sync(0xFFFFFFFFu, mxB, 2));
        float mn0 = fmaxf(m0, mxA), mn1 = fmaxf(m1, mxB);
        float c0 = exp2f(m0 - mn0), c1 = exp2f(m1 - mn1);
        m0 = mn0; m1 = mn1;

        // ---- P = exp2(s - m); keep partial sums in regs (reduce later)
        float sA = 0.f, sB = 0.f;
#pragma unroll
        for (int nt = 0; nt < 8; nt++) {
            float p0 = exp2f(s[nt][0] - mn0);
            float p1 = exp2f(s[nt][1] - mn0);
            float p2 = exp2f(s[nt][2] - mn1);
            float p3 = exp2f(s[nt][3] - mn1);
            sA += p0 + p1; sB += p2 + p3;
            s[nt][0] = __uint_as_float(f2tf32(p0));
            s[nt][1] = __uint_as_float(f2tf32(p1));
            s[nt][2] = __uint_as_float(f2tf32(p2));
            s[nt][3] = __uint_as_float(f2tf32(p3));
        }

        // ---- rescale O
#pragma unroll
        for (int nt = 0; nt < 16; nt++) {
            of[nt][0] *= c0; of[nt][1] *= c0;
            of[nt][2] *= c1; of[nt][3] *= c1;
        }

        // ---- O += P V : quad-shuffle P into a-frags
        const int srcA = (lane & ~3) | (q >> 1);
        const int srcB = srcA | 2;
        const bool odd = q & 1;
#pragma unroll
        for (int g = 0; g < 8; g++) {
            float a0A = __shfl_sync(0xFFFFFFFFu, s[g][0], srcA);
            float a1A = __shfl_sync(0xFFFFFFFFu, s[g][1], srcA);
            float b0A = __shfl_sync(0xFFFFFFFFu, s[g][2], srcA);
            float b1A = __shfl_sync(0xFFFFFFFFu, s[g][3], srcA);
            float a0B = __shfl_sync(0xFFFFFFFFu, s[g][0], srcB);
            float a1B = __shfl_sync(0xFFFFFFFFu, s[g][1], srcB);
            float b0B = __shfl_sync(0xFFFFFFFFu, s[g][2], srcB);
            float b1B = __shfl_sync(0xFFFFFFFFu, s[g][3], srcB);
            uint32_t pa[4];
            pa[0] = __float_as_uint(odd ? a1A : a0A);
            pa[1] = __float_as_uint(odd ? b1A : b0A);
            pa[2] = __float_as_uint(odd ? a1B : a0B);
            pa[3] = __float_as_uint(odd ? b1B : b0B);
            int k0 = g * 8 + q, k1 = g * 8 + q + 4;
#pragma unroll
            for (int nt = 0; nt < 16; nt++) {
                int dc = nt * 8 + r;
                uint32_t bf[2];
                bf[0] = __float_as_uint(Vst[k0 * VP + dc]);
                bf[1] = __float_as_uint(Vst[k1 * VP + dc]);
                mma1688(of[nt], pa, bf);
            }
        }

        // ---- deferred row-sum reduction (hidden under PV MMAs)
        sA += __shfl_xor_sync(0xFFFFFFFFu, sA, 1);
        sA += __shfl_xor_sync(0xFFFFFFFFu, sA, 2);
        sB += __shfl_xor_sync(0xFFFFFFFFu, sB, 1);
        sB += __shfl_xor_sync(0xFFFFFFFFu, sB, 2);
        l0 = l0 * c0 + sA;
        l1 = l1 * c1 + sB;
    }

    // epilogue: normalize + tf32-round (dense GEMM consumes rounded anyway)
    float li0 = 1.f / l0, li1 = 1.f / l1;
    int growA = qt * FQ + rA, growB = qt * FQ + rB;
#pragma unroll
    for (int nt = 0; nt < 16; nt++) {
        int col = h * HD + nt * 8 + 2 * q;
        *(float2*)(g_ctx + (size_t)(b * SEQ + growA) * HID + col) = make_float2(
            __uint_as_float(f2tf32(of[nt][0] * li0)),
            __uint_as_float(f2tf32(of[nt][1] * li0)));
        *(float2*)(g_ctx + (size_t)(b * SEQ + growB) * HID + col) = make_float2(
            __uint_as_float(f2tf32(of[nt][2] * li1)),
            __uint_as_float(f2tf32(of[nt][3] * li1)));
    }
}

// ---------------- launch ----------------
extern "C" void kernel_launch(void* const* d_in, const int* in_sizes, int n_in,
                              void* d_out, int out_size)
{
    const float* x    = (const float*)d_in[0];   // [B,S,H]
    const float* qkvw = (const float*)d_in[1];   // [H, 3H]
    const float* dw   = (const float*)d_in[2];   // [H, H]
    const float* rel  = (const float*)d_in[3];   // [32, 16]
    float* out = (float*)d_out;

    float *p_qkv, *p_ctx, *p_xr, *p_wqkvr, *p_dwr;
    cudaGetSymbolAddress((void**)&p_qkv,   g_qkv);
    cudaGetSymbolAddress((void**)&p_ctx,   g_ctx);
    cudaGetSymbolAddress((void**)&p_xr,    g_xr);
    cudaGetSymbolAddress((void**)&p_wqkvr, g_wqkvr);
    cudaGetSymbolAddress((void**)&p_dwr,   g_dwr);

    cudaFuncSetAttribute(gemm_mma, cudaFuncAttributeMaxDynamicSharedMemorySize, GEMM_SMEM);
    cudaFuncSetAttribute(flash_mma_kernel, cudaFuncAttributeMaxDynamicSharedMemorySize, FLASH_SMEM);

    // Launch order arranged so QKV GEMM is the 4th launch (ncu capture slot).
    // 1) RoPE tables
    rope_table_kernel<<<(SEQ * 64) / 256, 256>>>();
    // 2) round qkv_w
    tf32_round_kernel<<<(HID * 3 * HID / 4) / 256, 256>>>(qkvw, p_wqkvr);
    // 3) round x
    tf32_round_kernel<<<(BATCH * SEQ * HID / 4) / 256, 256>>>(x, p_xr);
    // 4) QKV GEMM (tf32 mma.sync)  <-- profiled launch
    gemm_mma<<<dim3(3 * HID / GBN, BATCH * SEQ / GBM), 256, GEMM_SMEM>>>(
        p_xr, p_wqkvr, p_qkv, BATCH * SEQ, 3 * HID, HID);
    // 5) round dense_w
    tf32_round_kernel<<<(HID * HID / 4) / 256, 256>>>(dw, p_dwr);
    // 6) RoPE + split + permute
    rope_split_kernel<<<(BATCH * SEQ * NHEADS * 64) / 256, 256>>>();
    // 7) bias table (pre-scaled)
    bias_kernel<<<(NHEADS * SEQ + 255) / 256, 256>>>(rel);
    // 8) flash attention
    flash_mma_kernel<<<dim3(SEQ / FQ, NHEADS, BATCH), 256, FLASH_SMEM>>>();
    // 9) dense GEMM
    gemm_mma<<<dim3(HID / GBN, BATCH * SEQ / GBM), 256, GEMM_SMEM>>>(
        p_ctx, p_dwr, out, BATCH * SEQ, HID, HID);
}

// round 9
// speedup vs baseline: 1.0788x; 1.0788x over previous
#include <cuda_runtime.h>
#include <math.h>
#include <float.h>
#include <stdint.h>

#define BATCH   2
#define SEQ     2048
#define HID     2048
#define NHEADS  16
#define HD      128

// ---------------- static scratch (no allocations allowed) ----------------
__device__ float g_qkv  [BATCH * SEQ * 3 * HID];       // [B,S,3H]
__device__ float g_Q    [BATCH * NHEADS * SEQ * HD];   // [B,NH,S,D] tf32
__device__ float g_K    [BATCH * NHEADS * SEQ * HD];   // tf32
__device__ float g_V    [BATCH * NHEADS * SEQ * HD];   // tf32
__device__ float g_ctx  [BATCH * SEQ * HID];           // [B,S,H] (tf32-rounded)
__device__ float g_bias [NHEADS * SEQ];                // bias[h][q-k] * log2(e)
__device__ float g_xr   [BATCH * SEQ * HID];           // tf32-rounded x
__device__ float g_wqkvr[HID * 3 * HID];               // tf32-rounded qkv_w
__device__ float g_dwr  [HID * HID];                   // tf32-rounded dense_w
__device__ float g_cos  [SEQ * 64];                    // RoPE tables
__device__ float g_sin  [SEQ * 64];

// ======================= helpers =======================
__device__ __forceinline__ uint32_t smem_u32(const void* p) {
    uint32_t a;
    asm("{ .reg .u64 t; cvta.to.shared.u64 t, %1; cvt.u32.u64 %0, t; }"
        : "=r"(a) : "l"(p));
    return a;
}
__device__ __forceinline__ uint32_t f2tf32(float x) {
    uint32_t r;
    asm("cvt.rna.tf32.f32 %0, %1;" : "=r"(r) : "f"(x));
    return r;
}
__device__ __forceinline__ void cp16(uint32_t s, const void* g) {
    asm volatile("cp.async.cg.shared.global [%0], [%1], 16;" :: "r"(s), "l"(g));
}
__device__ __forceinline__ void cp4(uint32_t s, const void* g) {
    asm volatile("cp.async.ca.shared.global [%0], [%1], 4;" :: "r"(s), "l"(g));
}
#define CP_COMMIT() asm volatile("cp.async.commit_group;" ::: "memory")
#define CP_WAIT2()  asm volatile("cp.async.wait_group 2;"  ::: "memory")
#define CP_WAIT1()  asm volatile("cp.async.wait_group 1;"  ::: "memory")
#define CP_WAIT0()  asm volatile("cp.async.wait_group 0;"  ::: "memory")

__device__ __forceinline__ void mma1688(float* d, const uint32_t* a, const uint32_t* b) {
    asm volatile(
        "mma.sync.aligned.m16n8k8.row.col.f32.tf32.tf32.f32 "
        "{%0,%1,%2,%3}, {%4,%5,%6,%7}, {%8,%9}, {%0,%1,%2,%3};"
        : "+f"(d[0]), "+f"(d[1]), "+f"(d[2]), "+f"(d[3])
        : "r"(a[0]), "r"(a[1]), "r"(a[2]), "r"(a[3]), "r"(b[0]), "r"(b[1]));
}

// ======================= tf32 pre-round (elementwise, float4) =======================
__global__ __launch_bounds__(256) void tf32_round_kernel(
    const float* __restrict__ in, float* __restrict__ out)
{
    int i = blockIdx.x * blockDim.x + threadIdx.x;
    float4 v = ((const float4*)in)[i];
    v.x = __uint_as_float(f2tf32(v.x));
    v.y = __uint_as_float(f2tf32(v.y));
    v.z = __uint_as_float(f2tf32(v.z));
    v.w = __uint_as_float(f2tf32(v.w));
    ((float4*)out)[i] = v;
}

// ======================= RoPE cos/sin table =======================
__global__ __launch_bounds__(256) void rope_table_kernel()
{
    int idx = blockIdx.x * blockDim.x + threadIdx.x;   // SEQ*64
    int s = idx >> 6, d = idx & 63;
    float inv = powf(10000.f, -(float)d * (1.f / 64.f));
    float sn, cs;
    sincosf((float)s * inv, &sn, &cs);
    g_cos[idx] = cs;
    g_sin[idx] = sn;
}

// ======================= tf32 mma.sync GEMM: 128x128 tile, 4 stages, occ 2 ==========
#define GBM 128
#define GBN 128
#define GBK 16
#define APITCH 20                  // 20r mod 32 distinct -> conflict-free a-frags
#define BPITCH 136                 // 136q mod 32 = 8q    -> conflict-free b-frags
#define A_STG (GBM * APITCH)       // 2560 floats
#define B_STG (GBK * BPITCH)       // 2176 floats
#define STG_FLOATS (A_STG + B_STG) // 4736 floats = 18944 B
#define GEMM_SMEM (4 * STG_FLOATS * 4)   // 75776 B -> 2 CTAs/SM

__global__ __launch_bounds__(256, 2) void gemm_mma(
    const float* __restrict__ A, const float* __restrict__ B,
    float* __restrict__ C, int M, int N, int K)
{
    extern __shared__ float sm[];
    const int tid  = threadIdx.x;
    const int warp = tid >> 5, lane = tid & 31;
    const int wm = (warp >> 2) * 64;
    const int wn = (warp & 3) * 32;
    const int r  = lane >> 2;
    const int q  = lane & 3;
    const int row0 = blockIdx.y * GBM;
    const int col0 = blockIdx.x * GBN;
    const uint32_t sb = smem_u32(sm);
    const int NC = K / GBK;

    float cf[4][4][4];
#pragma unroll
    for (int i = 0; i < 4; i++)
#pragma unroll
        for (int j = 0; j < 4; j++)
#pragma unroll
            for (int t = 0; t < 4; t++) cf[i][j][t] = 0.f;

    const int am  = tid >> 2;
    const int akq = (tid & 3) * 4;
    const int bk  = tid >> 5;
    const int bn4 = (tid & 31) * 4;

    auto load_stage = [&](int c, int s) {
        uint32_t base = sb + (uint32_t)(s * STG_FLOATS) * 4u;
        cp16(base + (uint32_t)((am      ) * APITCH + akq) * 4u,
             A + (size_t)(row0 + am      ) * K + c * GBK + akq);
        cp16(base + (uint32_t)((am + 64 ) * APITCH + akq) * 4u,
             A + (size_t)(row0 + am + 64 ) * K + c * GBK + akq);
        uint32_t bbase = base + (uint32_t)A_STG * 4u;
        cp16(bbase + (uint32_t)((bk    ) * BPITCH + bn4) * 4u,
             B + (size_t)(c * GBK + bk    ) * N + col0 + bn4);
        cp16(bbase + (uint32_t)((bk + 8) * BPITCH + bn4) * 4u,
             B + (size_t)(c * GBK + bk + 8) * N + col0 + bn4);
        CP_COMMIT();
    };

    load_stage(0, 0);
    load_stage(1, 1);
    load_stage(2, 2);

    for (int c = 0; c < NC; ++c) {
        CP_WAIT2();                    // stage c resident
        __syncthreads();               // all warps done reading stage (c+3)%4 (== c-1)
        int nc = c + 3;
        if (nc < NC) load_stage(nc, nc & 3); else CP_COMMIT();

        const float* As = sm + (c & 3) * STG_FLOATS;
        const float* Bs = As + A_STG;
#pragma unroll
        for (int k8 = 0; k8 < GBK; k8 += 8) {
            uint32_t af[4][4], bf[4][2];
#pragma unroll
            for (int mt = 0; mt < 4; mt++) {
                int row = wm + mt * 16 + r;
                af[mt][0] = __float_as_uint(As[(row    ) * APITCH + k8 + q    ]);
                af[mt][1] = __float_as_uint(As[(row + 8) * APITCH + k8 + q    ]);
                af[mt][2] = __float_as_uint(As[(row    ) * APITCH + k8 + q + 4]);
                af[mt][3] = __float_as_uint(As[(row + 8) * APITCH + k8 + q + 4]);
            }
#pragma unroll
            for (int nt = 0; nt < 4; nt++) {
                int cc = wn + nt * 8 + r;
                bf[nt][0] = __float_as_uint(Bs[(k8 + q    ) * BPITCH + cc]);
                bf[nt][1] = __float_as_uint(Bs[(k8 + q + 4) * BPITCH + cc]);
            }
#pragma unroll
            for (int mt = 0; mt < 4; mt++)
#pragma unroll
                for (int nt = 0; nt < 4; nt++)
                    mma1688(cf[mt][nt], af[mt], bf[nt]);
        }
    }

#pragma unroll
    for (int mt = 0; mt < 4; mt++) {
        int row = row0 + wm + mt * 16 + r;
#pragma unroll
        for (int nt = 0; nt < 4; nt++) {
            int col = col0 + wn + nt * 8 + 2 * q;
            *(float2*)(C + (size_t)row * N + col) =
                make_float2(cf[mt][nt][0], cf[mt][nt][1]);
            *(float2*)(C + (size_t)(row + 8) * N + col) =
                make_float2(cf[mt][nt][2], cf[mt][nt][3]);
        }
    }
}

// ---------------- RoPE + split + tf32 pre-round (natural d order) ----------------
__global__ __launch_bounds__(256) void rope_split_kernel()
{
    int t = blockIdx.x * blockDim.x + threadIdx.x;
    int d = t & 63;
    int h = (t >> 6) & (NHEADS - 1);
    int s = (t >> 10) & (SEQ - 1);
    int b = t >> 21;

    const float* base = g_qkv + ((size_t)(b * SEQ + s)) * (3 * HID) + h * HD;
    float q1 = base[d],            q2 = base[d + 64];
    float k1 = base[HID + d],      k2 = base[HID + d + 64];
    float v1 = base[2 * HID + d],  v2 = base[2 * HID + d + 64];

    float cs = g_cos[s * 64 + d];
    float sn = g_sin[s * 64 + d];

    size_t o = ((size_t)((b * NHEADS + h) * SEQ + s)) * HD;
    g_Q[o + d]      = __uint_as_float(f2tf32(q1 * cs - q2 * sn));
    g_Q[o + d + 64] = __uint_as_float(f2tf32(q2 * cs + q1 * sn));
    g_K[o + d]      = __uint_as_float(f2tf32(k1 * cs - k2 * sn));
    g_K[o + d + 64] = __uint_as_float(f2tf32(k2 * cs + k1 * sn));
    g_V[o + d]      = __uint_as_float(f2tf32(v1));
    g_V[o + d + 64] = __uint_as_float(f2tf32(v2));
}

// ---------------- relative-position bias table (pre-scaled by log2 e) ----------------
__global__ void bias_kernel(const float* __restrict__ rel)
{
    int idx = blockIdx.x * blockDim.x + threadIdx.x;
    if (idx >= NHEADS * SEQ) return;
    int h = idx >> 11;
    int n = idx & (SEQ - 1);
    int bucket;
    if (n < 16) {
        bucket = n;
    } else {
        float val = logf((float)n * (1.f / 16.f)) / logf(8.f) * 16.f;
        int bi = (int)val + 16;
        bucket = bi < 31 ? bi : 31;
    }
    g_bias[idx] = rel[bucket * NHEADS + h] * 1.4426950408889634f;
}

// ---------------- flash attention, FA2-style tf32 mma (R7 frag pattern) ----------------
#define FQ   128
#define FKC  64
#define QP   132
#define VP   136
#define OFF_FK (FQ * QP)
#define OFF_FV (OFF_FK + 2 * FKC * QP)
#define OFF_FB (OFF_FV + 2 * FKC * VP)
#define FLASH_FLOATS (OFF_FB + 2 * 192)
#define FLASH_SMEM (FLASH_FLOATS * 4)

__global__ __launch_bounds__(256, 1) void flash_mma_kernel()
{
    extern __shared__ float sm[];
    float* Qs = sm;

    const int qt = (int)gridDim.x - 1 - (int)blockIdx.x;   // heavy blocks first
    const int h = blockIdx.y, b = blockIdx.z;
    const int tid  = threadIdx.x;
    const int warp = tid >> 5, lane = tid & 31;
    const int r = lane >> 2, q = lane & 3;
    const int wr0 = warp * 16;
    const int rA = wr0 + r, rB = rA + 8;
    const uint32_t sbase = smem_u32(sm);

    const size_t headBase = (size_t)(b * NHEADS + h) * SEQ * HD;
    const float* Qg = g_Q + headBase + (size_t)qt * FQ * HD;
    const float* biasH = g_bias + h * SEQ;

    const float SCL2 = 0.08838834764831845f * 1.4426950408889634f;

    // prolog: Q (group0), then KV tile 0 + bias0 (group1)
#pragma unroll
    for (int i = 0; i < 16; i++) {
        int f = tid + i * 256; int rr = f >> 5, c4 = (f & 31) * 4;
        cp16(sbase + (uint32_t)(rr * QP + c4) * 4u, Qg + rr * HD + c4);
    }
    CP_COMMIT();
    {
        const float* Kg = g_K + headBase;
        const float* Vg = g_V + headBase;
#pragma unroll
        for (int i = 0; i < 8; i++) {
            int f = tid + i * 256; int rr = f >> 5, c4 = (f & 31) * 4;
            cp16(sbase + (uint32_t)(OFF_FK + rr * QP + c4) * 4u, Kg + rr * HD + c4);
            cp16(sbase + (uint32_t)(OFF_FV + rr * VP + c4) * 4u, Vg + rr * HD + c4);
        }
        if (tid < 192) {
            int dl = qt * FQ + tid - 63;
            cp4(sbase + (uint32_t)(OFF_FB + tid) * 4u, biasH + (dl >= 0 ? dl : 0));
        }
        CP_COMMIT();
    }
    CP_WAIT1();                        // Q done
    __syncthreads();

    // hoist Q fragments to registers (scalar, conflict-free 4r+q pattern)
    uint32_t qf[16][4];
#pragma unroll
    for (int k8 = 0; k8 < 16; k8++) {
        int kc = k8 * 8;
        qf[k8][0] = __float_as_uint(Qs[rA * QP + kc + q]);
        qf[k8][1] = __float_as_uint(Qs[rB * QP + kc + q]);
        qf[k8][2] = __float_as_uint(Qs[rA * QP + kc + q + 4]);
        qf[k8][3] = __float_as_uint(Qs[rB * QP + kc + q + 4]);
    }

    float m0 = -1e30f, m1 = -1e30f, l0 = 0.f, l1 = 0.f;
    float of[16][4];
#pragma unroll
    for (int nt = 0; nt < 16; nt++)
#pragma unroll
        for (int e = 0; e < 4; e++) of[nt][e] = 0.f;

    const int NT = 2 * qt + 2;

    for (int kt = 0; kt < NT; ++kt) {
        __syncthreads();
        if (kt + 1 < NT) {
            const int ns = (kt + 1) & 1;
            const float* Kg = g_K + headBase + (size_t)(kt + 1) * FKC * HD;
            const float* Vg = g_V + headBase + (size_t)(kt + 1) * FKC * HD;
#pragma unroll
            for (int i = 0; i < 8; i++) {
                int f = tid + i * 256; int rr = f >> 5, c4 = (f & 31) * 4;
                cp16(sbase + (uint32_t)(OFF_FK + ns * FKC * QP + rr * QP + c4) * 4u, Kg + rr * HD + c4);
                cp16(sbase + (uint32_t)(OFF_FV + ns * FKC * VP + rr * VP + c4) * 4u, Vg + rr * HD + c4);
            }
            if (tid < 192) {
                int dl = qt * FQ - (kt + 1) * FKC + tid - 63;
                cp4(sbase + (uint32_t)(OFF_FB + ns * 192 + tid) * 4u,
                    biasH + (dl >= 0 ? dl : 0));
            }
            CP_COMMIT();
            CP_WAIT1();
        } else {
            CP_WAIT0();
        }
        __syncthreads();

        const int base = qt * FQ - kt * FKC;
        if (base < -(wr0 + 15)) continue;       // fully-masked warp

        const float* Kst = sm + OFF_FK + (kt & 1) * FKC * QP;
        const float* Vst = sm + OFF_FV + (kt & 1) * FKC * VP;
        const float* bsm = sm + OFF_FB + (kt & 1) * 192;

        // ---- S = Q K^T (16 x 64 per warp)
        float s[8][4];
#pragma unroll
        for (int nt = 0; nt < 8; nt++)
#pragma unroll
            for (int e = 0; e < 4; e++) s[nt][e] = 0.f;

#pragma unroll
        for (int k8 = 0; k8 < 16; k8++) {
            int kc = k8 * 8;
#pragma unroll
            for (int nt = 0; nt < 8; nt++) {
                uint32_t bf[2];
                bf[0] = __float_as_uint(Kst[(nt * 8 + r) * QP + kc + q]);
                bf[1] = __float_as_uint(Kst[(nt * 8 + r) * QP + kc + q + 4]);
                mma1688(s[nt], qf[k8], bf);
            }
        }

        // ---- scale + bias (pre-scaled by log2e) + causal mask
        const bool dg = (base < FQ);
#pragma unroll
        for (int nt = 0; nt < 8; nt++) {
            int lc = nt * 8 + 2 * q;
            float v0 = s[nt][0] * SCL2 + bsm[rA - lc + 63];
            float v1 = s[nt][1] * SCL2 + bsm[rA - lc + 62];
            float v2 = s[nt][2] * SCL2 + bsm[rB - lc + 63];
            float v3 = s[nt][3] * SCL2 + bsm[rB - lc + 62];
            s[nt][0] = (dg && lc     > rA + base) ? -1e30f : v0;
            s[nt][1] = (dg && lc + 1 > rA + base) ? -1e30f : v1;
            s[nt][2] = (dg && lc     > rB + base) ? -1e30f : v2;
            s[nt][3] = (dg && lc + 1 > rB + base) ? -1e30f : v3;
        }

        // ---- row max within quad
        float mxA = -1e30f, mxB = -1e30f;
#pragma unroll
        for (int nt = 0; nt < 8; nt++) {
            mxA = fmaxf(mxA, fmaxf(s[nt][0], s[nt][1]));
            mxB = fmaxf(mxB, fmaxf(s[nt][2], s[nt][3]));
        }
        mxA = fmaxf(mxA, __shfl_xor_sync(0xFFFFFFFFu, mxA, 1));
        mxA = fmaxf(mxA, __shfl_xor_sync(0xFFFFFFFFu, mxA, 2));
        mxB = fmaxf(mxB, __shfl_xor_sync(0xFFFFFFFFu, mxB, 1));
        mxB = fmaxf(mxB, __shfl_xor_sync(0xFFFFFFFFu, mxB, 2));
        float mn0 = fmaxf(m0, mxA), mn1 = fmaxf(m1, mxB);
        float c0 = exp2f(m0 - mn0), c1 = exp2f(m1 - mn1);
        m0 = mn0; m1 = mn1;

        // ---- P = exp2(s - m); keep partial sums in regs (reduce later)
        float sA = 0.f, sB = 0.f;
#pragma unroll
        for (int nt = 0; nt < 8; nt++) {
            float p0 = exp2f(s[nt][0] - mn0);
            float p1 = exp2f(s[nt][1] - mn0);
            float p2 = exp2f(s[nt][2] - mn1);
            float p3 = exp2f(s[nt][3] - mn1);
            sA += p0 + p1; sB += p2 + p3;
            s[nt][0] = __uint_as_float(f2tf32(p0));
            s[nt][1] = __uint_as_float(f2tf32(p1));
            s[nt][2] = __uint_as_float(f2tf32(p2));
            s[nt][3] = __uint_as_float(f2tf32(p3));
        }

        // ---- rescale O
#pragma unroll
        for (int nt = 0; nt < 16; nt++) {
            of[nt][0] *= c0; of[nt][1] *= c0;
            of[nt][2] *= c1; of[nt][3] *= c1;
        }

        // ---- O += P V : quad-shuffle P into a-frags
        const int srcA = (lane & ~3) | (q >> 1);
        const int srcB = srcA | 2;
        const bool odd = q & 1;
#pragma unroll
        for (int g = 0; g < 8; g++) {
            float a0A = __shfl_sync(0xFFFFFFFFu, s[g][0], srcA);
            float a1A = __shfl_sync(0xFFFFFFFFu, s[g][1], srcA);
            float b0A = __shfl_sync(0xFFFFFFFFu, s[g][2], srcA);
            float b1A = __shfl_sync(0xFFFFFFFFu, s[g][3], srcA);
            float a0B = __shfl_sync(0xFFFFFFFFu, s[g][0], srcB);
            float a1B = __shfl_sync(0xFFFFFFFFu, s[g][1], srcB);
            float b0B = __shfl_sync(0xFFFFFFFFu, s[g][2], srcB);
            float b1B = __shfl_sync(0xFFFFFFFFu, s[g][3], srcB);
            uint32_t pa[4];
            pa[0] = __float_as_uint(odd ? a1A : a0A);
            pa[1] = __float_as_uint(odd ? b1A : b0A);
            pa[2] = __float_as_uint(odd ? a1B : a0B);
            pa[3] = __float_as_uint(odd ? b1B : b0B);
            int k0 = g * 8 + q, k1 = g * 8 + q + 4;
#pragma unroll
            for (int nt = 0; nt < 16; nt++) {
                int dc = nt * 8 + r;
                uint32_t bf[2];
                bf[0] = __float_as_uint(Vst[k0 * VP + dc]);
                bf[1] = __float_as_uint(Vst[k1 * VP + dc]);
                mma1688(of[nt], pa, bf);
            }
        }

        // ---- deferred row-sum reduction (hidden under PV MMAs)
        sA += __shfl_xor_sync(0xFFFFFFFFu, sA, 1);
        sA += __shfl_xor_sync(0xFFFFFFFFu, sA, 2);
        sB += __shfl_xor_sync(0xFFFFFFFFu, sB, 1);
        sB += __shfl_xor_sync(0xFFFFFFFFu, sB, 2);
        l0 = l0 * c0 + sA;
        l1 = l1 * c1 + sB;
    }

    // epilogue: normalize + tf32-round (dense GEMM consumes rounded anyway)
    float li0 = 1.f / l0, li1 = 1.f / l1;
    int growA = qt * FQ + rA, growB = qt * FQ + rB;
#pragma unroll
    for (int nt = 0; nt < 16; nt++) {
        int col = h * HD + nt * 8 + 2 * q;
        *(float2*)(g_ctx + (size_t)(b * SEQ + growA) * HID + col) = make_float2(
            __uint_as_float(f2tf32(of[nt][0] * li0)),
            __uint_as_float(f2tf32(of[nt][1] * li0)));
        *(float2*)(g_ctx + (size_t)(b * SEQ + growB) * HID + col) = make_float2(
            __uint_as_float(f2tf32(of[nt][2] * li1)),
            __uint_as_float(f2tf32(of[nt][3] * li1)));
    }
}

// ---------------- launch ----------------
extern "C" void kernel_launch(void* const* d_in, const int* in_sizes, int n_in,
                              void* d_out, int out_size)
{
    const float* x    = (const float*)d_in[0];   // [B,S,H]
    const float* qkvw = (const float*)d_in[1];   // [H, 3H]
    const float* dw   = (const float*)d_in[2];   // [H, H]
    const float* rel  = (const float*)d_in[3];   // [32, 16]
    float* out = (float*)d_out;

    float *p_qkv, *p_ctx, *p_xr, *p_wqkvr, *p_dwr;
    cudaGetSymbolAddress((void**)&p_qkv,   g_qkv);
    cudaGetSymbolAddress((void**)&p_ctx,   g_ctx);
    cudaGetSymbolAddress((void**)&p_xr,    g_xr);
    cudaGetSymbolAddress((void**)&p_wqkvr, g_wqkvr);
    cudaGetSymbolAddress((void**)&p_dwr,   g_dwr);

    cudaFuncSetAttribute(gemm_mma, cudaFuncAttributeMaxDynamicSharedMemorySize, GEMM_SMEM);
    cudaFuncSetAttribute(flash_mma_kernel, cudaFuncAttributeMaxDynamicSharedMemorySize, FLASH_SMEM);

    // Launch order keeps QKV GEMM as the 4th launch (ncu capture slot).
    rope_table_kernel<<<(SEQ * 64) / 256, 256>>>();
    tf32_round_kernel<<<(HID * 3 * HID / 4) / 256, 256>>>(qkvw, p_wqkvr);
    tf32_round_kernel<<<(BATCH * SEQ * HID / 4) / 256, 256>>>(x, p_xr);
    // 4) QKV GEMM  <-- profiled launch
    gemm_mma<<<dim3(3 * HID / GBN, BATCH * SEQ / GBM), 256, GEMM_SMEM>>>(
        p_xr, p_wqkvr, p_qkv, BATCH * SEQ, 3 * HID, HID);
    tf32_round_kernel<<<(HID * HID / 4) / 256, 256>>>(dw, p_dwr);
    rope_split_kernel<<<(BATCH * SEQ * NHEADS * 64) / 256, 256>>>();
    bias_kernel<<<(NHEADS * SEQ + 255) / 256, 256>>>(rel);
    flash_mma_kernel<<<dim3(SEQ / FQ, NHEADS, BATCH), 256, FLASH_SMEM>>>();
    gemm_mma<<<dim3(HID / GBN, BATCH * SEQ / GBM), 256, GEMM_SMEM>>>(
        p_ctx, p_dwr, out, BATCH * SEQ, HID, HID);
}

// round 10
// speedup vs baseline: 1.7004x; 1.5762x over previous
#include <cuda_runtime.h>
#include <cuda_fp16.h>
#include <math.h>
#include <float.h>
#include <stdint.h>

#define BATCH   2
#define SEQ     2048
#define HID     2048
#define NHEADS  16
#define HD      128

// ---------------- static scratch (no allocations allowed) ----------------
__device__ __half g_qkvh [BATCH * SEQ * 3 * HID];       // [B,S,3H] fp16 (QKV gemm out)
__device__ __half g_Qh   [BATCH * NHEADS * SEQ * HD];   // [B,NH,S,D]
__device__ __half g_Kh   [BATCH * NHEADS * SEQ * HD];
__device__ __half g_Vh   [BATCH * NHEADS * SEQ * HD];
__device__ __half g_VTh  [BATCH * NHEADS * HD * SEQ];   // [B,NH,D,S]
__device__ __half g_ctxh [BATCH * SEQ * HID];           // [B,S,H]
__device__ __half g_xh   [BATCH * SEQ * HID];           // fp16 x
__device__ __half g_wqkvh[3 * HID * HID];               // [3H,H]  qkv_w^T fp16
__device__ __half g_dwh  [HID * HID];                   // [H,H]   dense_w^T fp16
__device__ float  g_bias [NHEADS * SEQ];                // bias[h][q-k] * log2(e)
__device__ float  g_cos  [SEQ * 64];
__device__ float  g_sin  [SEQ * 64];

// ======================= helpers =======================
__device__ __forceinline__ uint32_t smem_u32(const void* p) {
    uint32_t a;
    asm("{ .reg .u64 t; cvta.to.shared.u64 t, %1; cvt.u32.u64 %0, t; }"
        : "=r"(a) : "l"(p));
    return a;
}
__device__ __forceinline__ void cp16(uint32_t s, const void* g) {
    asm volatile("cp.async.cg.shared.global [%0], [%1], 16;" :: "r"(s), "l"(g));
}
__device__ __forceinline__ void cp4(uint32_t s, const void* g) {
    asm volatile("cp.async.ca.shared.global [%0], [%1], 4;" :: "r"(s), "l"(g));
}
#define CP_COMMIT() asm volatile("cp.async.commit_group;" ::: "memory")
#define CP_WAIT2()  asm volatile("cp.async.wait_group 2;"  ::: "memory")
#define CP_WAIT1()  asm volatile("cp.async.wait_group 1;"  ::: "memory")
#define CP_WAIT0()  asm volatile("cp.async.wait_group 0;"  ::: "memory")

__device__ __forceinline__ uint32_t ld32h(const __half* p) {
    return *(const uint32_t*)p;
}
__device__ __forceinline__ uint32_t packh2(float x, float y) {
    __half2 h = __floats2half2_rn(x, y);
    return *(uint32_t*)&h;
}

// fp16 mma: D(f32) += A(f16 m16k16, row) * B(f16 k16n8, col)
__device__ __forceinline__ void mma16816(float* d, const uint32_t* a, const uint32_t* b) {
    asm volatile(
        "mma.sync.aligned.m16n8k16.row.col.f32.f16.f16.f32 "
        "{%0,%1,%2,%3}, {%4,%5,%6,%7}, {%8,%9}, {%0,%1,%2,%3};"
        : "+f"(d[0]), "+f"(d[1]), "+f"(d[2]), "+f"(d[3])
        : "r"(a[0]), "r"(a[1]), "r"(a[2]), "r"(a[3]), "r"(b[0]), "r"(b[1]));
}

// ======================= f32 -> f16 convert (elementwise) =======================
__global__ __launch_bounds__(256) void convert_h_kernel(
    const float* __restrict__ in, __half* __restrict__ out)
{
    int i = blockIdx.x * blockDim.x + threadIdx.x;
    float4 v = ((const float4*)in)[i];
    __half2* o = (__half2*)out;
    o[2 * i]     = __floats2half2_rn(v.x, v.y);
    o[2 * i + 1] = __floats2half2_rn(v.z, v.w);
}

// ======================= f32 [R][C] -> f16 [C][R] transpose =======================
__global__ __launch_bounds__(256) void transpose_h_kernel(
    const float* __restrict__ in, __half* __restrict__ out, int R, int C)
{
    __shared__ float t[32][33];
    int bx = blockIdx.x * 32, by = blockIdx.y * 32;
    int tx = threadIdx.x & 31, ty = threadIdx.x >> 5;
#pragma unroll
    for (int i = 0; i < 32; i += 8)
        t[ty + i][tx] = in[(size_t)(by + ty + i) * C + bx + tx];
    __syncthreads();
#pragma unroll
    for (int i = 0; i < 32; i += 8)
        out[(size_t)(bx + ty + i) * R + by + tx] = __float2half_rn(t[tx][ty + i]);
}

// ======================= RoPE cos/sin table =======================
__global__ __launch_bounds__(256) void rope_table_kernel()
{
    int idx = blockIdx.x * blockDim.x + threadIdx.x;   // SEQ*64
    int s = idx >> 6, d = idx & 63;
    float inv = powf(10000.f, -(float)d * (1.f / 64.f));
    float sn, cs;
    sincosf((float)s * inv, &sn, &cs);
    g_cos[idx] = cs;
    g_sin[idx] = sn;
}

// ======================= fp16 mma GEMM: C[M,N] = A[M,K] @ Bt[N,K]^T ================
// 128x128 C-tile, chunk = 32 k-halves (2 k16 steps), 4 stages, occ 2.
#define GBM 128
#define GBN 128
#define GBKH 32                      // k halves per chunk
#define GPITCH 40                    // halves; word pitch 20 -> conflict-free frags
#define STG_HALFS (2 * 128 * GPITCH) // A + B = 10240 halves = 20480 B
#define GEMM_SMEM (4 * STG_HALFS * 2)   // 81920 B -> 2 CTAs/SM

template <typename OutT>
__global__ __launch_bounds__(256, 2) void gemm_h(
    const __half* __restrict__ A, const __half* __restrict__ Bt,
    OutT* __restrict__ C, int M, int N, int K)
{
    extern __shared__ __half smh[];
    const int tid  = threadIdx.x;
    const int warp = tid >> 5, lane = tid & 31;
    const int wm = (warp >> 2) * 64;
    const int wn = (warp & 3) * 32;
    const int r  = lane >> 2;
    const int q  = lane & 3;
    const int row0 = blockIdx.y * GBM;
    const int col0 = blockIdx.x * GBN;
    const uint32_t sb = smem_u32(smh);
    const int NC = K / GBKH;

    float cf[4][4][4];
#pragma unroll
    for (int i = 0; i < 4; i++)
#pragma unroll
        for (int j = 0; j < 4; j++)
#pragma unroll
            for (int t = 0; t < 4; t++) cf[i][j][t] = 0.f;

    const int lrow = tid >> 1;              // 0..127
    const int lseg = (tid & 1) * 2;         // 0 or 2 (16-byte segs of 8 halves)

    auto load_stage = [&](int c, int s) {
        uint32_t base = sb + (uint32_t)(s * STG_HALFS) * 2u;
#pragma unroll
        for (int j = 0; j < 2; j++) {
            int seg = lseg + j;
            cp16(base + (uint32_t)(lrow * GPITCH + seg * 8) * 2u,
                 A + (size_t)(row0 + lrow) * K + c * GBKH + seg * 8);
            cp16(base + (uint32_t)(128 * GPITCH + lrow * GPITCH + seg * 8) * 2u,
                 Bt + (size_t)(col0 + lrow) * K + c * GBKH + seg * 8);
        }
        CP_COMMIT();
    };

    load_stage(0, 0);
    load_stage(1, 1);
    load_stage(2, 2);

    for (int c = 0; c < NC; ++c) {
        CP_WAIT2();
        __syncthreads();
        int nc = c + 3;
        if (nc < NC) load_stage(nc, nc & 3); else CP_COMMIT();

        const __half* As = smh + (c & 3) * STG_HALFS;
        const __half* Bs = As + 128 * GPITCH;
#pragma unroll
        for (int step = 0; step < 2; step++) {
            const int kk = step * 16;
            uint32_t af[4][4], bf[4][2];
#pragma unroll
            for (int mt = 0; mt < 4; mt++) {
                int row = wm + mt * 16 + r;
                af[mt][0] = ld32h(As + (row    ) * GPITCH + kk + 2 * q);
                af[mt][1] = ld32h(As + (row + 8) * GPITCH + kk + 2 * q);
                af[mt][2] = ld32h(As + (row    ) * GPITCH + kk + 8 + 2 * q);
                af[mt][3] = ld32h(As + (row + 8) * GPITCH + kk + 8 + 2 * q);
            }
#pragma unroll
            for (int nt = 0; nt < 4; nt++) {
                int cc = wn + nt * 8 + r;
                bf[nt][0] = ld32h(Bs + cc * GPITCH + kk + 2 * q);
                bf[nt][1] = ld32h(Bs + cc * GPITCH + kk + 8 + 2 * q);
            }
#pragma unroll
            for (int mt = 0; mt < 4; mt++)
#pragma unroll
                for (int nt = 0; nt < 4; nt++)
                    mma16816(cf[mt][nt], af[mt], bf[nt]);
        }
    }

#pragma unroll
    for (int mt = 0; mt < 4; mt++) {
        int row = row0 + wm + mt * 16 + r;
#pragma unroll
        for (int nt = 0; nt < 4; nt++) {
            int col = col0 + wn + nt * 8 + 2 * q;
            if (sizeof(OutT) == 2) {
                *(__half2*)((__half*)C + (size_t)row * N + col) =
                    __floats2half2_rn(cf[mt][nt][0], cf[mt][nt][1]);
                *(__half2*)((__half*)C + (size_t)(row + 8) * N + col) =
                    __floats2half2_rn(cf[mt][nt][2], cf[mt][nt][3]);
            } else {
                *(float2*)((float*)C + (size_t)row * N + col) =
                    make_float2(cf[mt][nt][0], cf[mt][nt][1]);
                *(float2*)((float*)C + (size_t)(row + 8) * N + col) =
                    make_float2(cf[mt][nt][2], cf[mt][nt][3]);
            }
        }
    }
}

// ---------------- RoPE + split (fp16 in/out) ----------------
__global__ __launch_bounds__(256) void rope_split_kernel()
{
    int t = blockIdx.x * blockDim.x + threadIdx.x;
    int d = t & 63;
    int h = (t >> 6) & (NHEADS - 1);
    int s = (t >> 10) & (SEQ - 1);
    int b = t >> 21;

    const __half* base = g_qkvh + ((size_t)(b * SEQ + s)) * (3 * HID) + h * HD;
    float q1 = __half2float(base[d]),            q2 = __half2float(base[d + 64]);
    float k1 = __half2float(base[HID + d]),      k2 = __half2float(base[HID + d + 64]);
    float v1 = __half2float(base[2 * HID + d]),  v2 = __half2float(base[2 * HID + d + 64]);

    float cs = g_cos[s * 64 + d];
    float sn = g_sin[s * 64 + d];

    size_t o = ((size_t)((b * NHEADS + h) * SEQ + s)) * HD;
    g_Qh[o + d]      = __float2half_rn(q1 * cs - q2 * sn);
    g_Qh[o + d + 64] = __float2half_rn(q2 * cs + q1 * sn);
    g_Kh[o + d]      = __float2half_rn(k1 * cs - k2 * sn);
    g_Kh[o + d + 64] = __float2half_rn(k2 * cs + k1 * sn);
    g_Vh[o + d]      = __float2half_rn(v1);
    g_Vh[o + d + 64] = __float2half_rn(v2);
}

// ---------------- V transpose: [B,NH,S,D] -> [B,NH,D,S] ----------------
__global__ __launch_bounds__(256) void vtrans_kernel()
{
    __shared__ __half t[32][33];
    int s0 = blockIdx.x * 32, d0 = blockIdx.y * 32;
    size_t base = (size_t)blockIdx.z * SEQ * HD;
    int tx = threadIdx.x & 31, ty = threadIdx.x >> 5;
#pragma unroll
    for (int i = 0; i < 32; i += 8)
        t[ty + i][tx] = g_Vh[base + (size_t)(s0 + ty + i) * HD + d0 + tx];
    __syncthreads();
#pragma unroll
    for (int i = 0; i < 32; i += 8)
        g_VTh[base + (size_t)(d0 + ty + i) * SEQ + s0 + tx] = t[tx][ty + i];
}

// ---------------- relative-position bias table (pre-scaled by log2 e) ----------------
__global__ void bias_kernel(const float* __restrict__ rel)
{
    int idx = blockIdx.x * blockDim.x + threadIdx.x;
    if (idx >= NHEADS * SEQ) return;
    int h = idx >> 11;
    int n = idx & (SEQ - 1);
    int bucket;
    if (n < 16) {
        bucket = n;
    } else {
        float val = logf((float)n * (1.f / 16.f)) / logf(8.f) * 16.f;
        int bi = (int)val + 16;
        bucket = bi < 31 ? bi : 31;
    }
    g_bias[idx] = rel[bucket * NHEADS + h] * 1.4426950408889634f;
}

// ---------------- flash attention, fp16 mma (no P shuffle) ----------------
// 128 q-rows per block, 64 k-cols per iter. Q/K [row][d] pitch 136; VT [d][key] pitch 72.
#define FQ   128
#define FKC  64
#define QPH  136
#define VTPH 72
#define OFF_KH  (FQ * QPH)                 // 17408 halves
#define OFF_VTH (OFF_KH + 2 * FKC * QPH)   // 34816 halves
#define OFF_BB  ((OFF_VTH + 2 * HD * VTPH) * 2)   // byte offset of bias floats: 106496
#define FLASH_SMEM (OFF_BB + 2 * 192 * 4)         // 108032 B

__global__ __launch_bounds__(256, 1) void flash_mma_kernel()
{
    extern __shared__ __half smh[];
    __half* Qs = smh;
    float* biasb = (float*)((char*)smh + OFF_BB);

    const int qt = (int)gridDim.x - 1 - (int)blockIdx.x;   // heavy blocks first
    const int h = blockIdx.y, b = blockIdx.z;
    const int tid  = threadIdx.x;
    const int warp = tid >> 5, lane = tid & 31;
    const int r = lane >> 2, q = lane & 3;
    const int wr0 = warp * 16;
    const int rA = wr0 + r, rB = rA + 8;
    const uint32_t sbase = smem_u32(smh);

    const size_t headBase = (size_t)(b * NHEADS + h) * SEQ * HD;
    const __half* Qg  = g_Qh + headBase + (size_t)qt * FQ * HD;
    const __half* VTg = g_VTh + headBase;
    const float* biasH = g_bias + h * SEQ;

    const float SCL2 = 0.08838834764831845f * 1.4426950408889634f;

    // prolog: Q (group0), then K/VT tile 0 + bias0 (group1)
#pragma unroll
    for (int i = 0; i < 8; i++) {
        int f = tid + i * 256; int rr = f >> 4, c16 = f & 15;
        cp16(sbase + (uint32_t)(rr * QPH + c16 * 8) * 2u, Qg + rr * HD + c16 * 8);
    }
    CP_COMMIT();
    {
        const __half* Kg = g_Kh + headBase;
#pragma unroll
        for (int i = 0; i < 4; i++) {
            int f = tid + i * 256;
            int rr = f >> 4, c16 = f & 15;
            cp16(sbase + (uint32_t)(OFF_KH + rr * QPH + c16 * 8) * 2u, Kg + rr * HD + c16 * 8);
            int vr = f >> 3, c8 = f & 7;
            cp16(sbase + (uint32_t)(OFF_VTH + vr * VTPH + c8 * 8) * 2u, VTg + (size_t)vr * SEQ + c8 * 8);
        }
        if (tid < 192) {
            int dl = qt * FQ + tid - 63;
            cp4(sbase + (uint32_t)OFF_BB + tid * 4u, biasH + (dl >= 0 ? dl : 0));
        }
        CP_COMMIT();
    }
    CP_WAIT1();                        // Q resident
    __syncthreads();

    // hoist Q fragments (8 k16 steps x 4 regs)
    uint32_t qf[8][4];
#pragma unroll
    for (int g = 0; g < 8; g++) {
        qf[g][0] = ld32h(Qs + rA * QPH + g * 16 + 2 * q);
        qf[g][1] = ld32h(Qs + rB * QPH + g * 16 + 2 * q);
        qf[g][2] = ld32h(Qs + rA * QPH + g * 16 + 8 + 2 * q);
        qf[g][3] = ld32h(Qs + rB * QPH + g * 16 + 8 + 2 * q);
    }

    float m0 = -1e30f, m1 = -1e30f, l0 = 0.f, l1 = 0.f;
    float of[16][4];
#pragma unroll
    for (int nt = 0; nt < 16; nt++)
#pragma unroll
        for (int e = 0; e < 4; e++) of[nt][e] = 0.f;

    const int NT = 2 * qt + 2;

    for (int kt = 0; kt < NT; ++kt) {
        __syncthreads();
        if (kt + 1 < NT) {
            const int ns = (kt + 1) & 1;
            const __half* Kg = g_Kh + headBase + (size_t)(kt + 1) * FKC * HD;
            const int keyb = (kt + 1) * FKC;
#pragma unroll
            for (int i = 0; i < 4; i++) {
                int f = tid + i * 256;
                int rr = f >> 4, c16 = f & 15;
                cp16(sbase + (uint32_t)(OFF_KH + ns * FKC * QPH + rr * QPH + c16 * 8) * 2u,
                     Kg + rr * HD + c16 * 8);
                int vr = f >> 3, c8 = f & 7;
                cp16(sbase + (uint32_t)(OFF_VTH + ns * HD * VTPH + vr * VTPH + c8 * 8) * 2u,
                     VTg + (size_t)vr * SEQ + keyb + c8 * 8);
            }
            if (tid < 192) {
                int dl = qt * FQ - (kt + 1) * FKC + tid - 63;
                cp4(sbase + (uint32_t)OFF_BB + (ns * 192 + tid) * 4u,
                    biasH + (dl >= 0 ? dl : 0));
            }
            CP_COMMIT();
            CP_WAIT1();
        } else {
            CP_WAIT0();
        }
        __syncthreads();

        const int base = qt * FQ - kt * FKC;
        if (base < -(wr0 + 15)) continue;       // fully-masked warp

        const __half* Kst  = smh + OFF_KH  + (kt & 1) * FKC * QPH;
        const __half* VTst = smh + OFF_VTH + (kt & 1) * HD * VTPH;
        const float* bsm = biasb + (kt & 1) * 192;

        // ---- S = Q K^T (16 x 64 per warp): 8 k16 steps x 8 n-tiles
        float s[8][4];
#pragma unroll
        for (int nt = 0; nt < 8; nt++)
#pragma unroll
            for (int e = 0; e < 4; e++) s[nt][e] = 0.f;

#pragma unroll
        for (int g = 0; g < 8; g++) {
#pragma unroll
            for (int nt = 0; nt < 8; nt++) {
                uint32_t bf[2];
                bf[0] = ld32h(Kst + (nt * 8 + r) * QPH + g * 16 + 2 * q);
                bf[1] = ld32h(Kst + (nt * 8 + r) * QPH + g * 16 + 8 + 2 * q);
                mma16816(s[nt], qf[g], bf);
            }
        }

        // ---- scale + bias + causal mask
        const bool dg = (base < FQ);
#pragma unroll
        for (int nt = 0; nt < 8; nt++) {
            int lc = nt * 8 + 2 * q;
            float v0 = s[nt][0] * SCL2 + bsm[rA - lc + 63];
            float v1 = s[nt][1] * SCL2 + bsm[rA - lc + 62];
            float v2 = s[nt][2] * SCL2 + bsm[rB - lc + 63];
            float v3 = s[nt][3] * SCL2 + bsm[rB - lc + 62];
            s[nt][0] = (dg && lc     > rA + base) ? -1e30f : v0;
            s[nt][1] = (dg && lc + 1 > rA + base) ? -1e30f : v1;
            s[nt][2] = (dg && lc     > rB + base) ? -1e30f : v2;
            s[nt][3] = (dg && lc + 1 > rB + base) ? -1e30f : v3;
        }

        // ---- row max within quad
        float mxA = -1e30f, mxB = -1e30f;
#pragma unroll
        for (int nt = 0; nt < 8; nt++) {
            mxA = fmaxf(mxA, fmaxf(s[nt][0], s[nt][1]));
            mxB = fmaxf(mxB, fmaxf(s[nt][2], s[nt][3]));
        }
        mxA = fmaxf(mxA, __shfl_xor_sync(0xFFFFFFFFu, mxA, 1));
        mxA = fmaxf(mxA, __shfl_xor_sync(0xFFFFFFFFu, mxA, 2));
        mxB = fmaxf(mxB, __shfl_xor_sync(0xFFFFFFFFu, mxB, 1));
        mxB = fmaxf(mxB, __shfl_xor_sync(0xFFFFFFFFu, mxB, 2));
        float mn0 = fmaxf(m0, mxA), mn1 = fmaxf(m1, mxB);
        float c0 = exp2f(m0 - mn0), c1 = exp2f(m1 - mn1);
        m0 = mn0; m1 = mn1;

        // ---- P = exp2(s - m); partial sums
        float sA = 0.f, sB = 0.f;
#pragma unroll
        for (int nt = 0; nt < 8; nt++) {
            s[nt][0] = exp2f(s[nt][0] - mn0);
            s[nt][1] = exp2f(s[nt][1] - mn0);
            s[nt][2] = exp2f(s[nt][2] - mn1);
            s[nt][3] = exp2f(s[nt][3] - mn1);
            sA += s[nt][0] + s[nt][1];
            sB += s[nt][2] + s[nt][3];
        }

        // ---- rescale O
#pragma unroll
        for (int nt = 0; nt < 16; nt++) {
            of[nt][0] *= c0; of[nt][1] *= c0;
            of[nt][2] *= c1; of[nt][3] *= c1;
        }

        // ---- O += P V : P already in A-frag layout (no shuffles!)
#pragma unroll
        for (int g = 0; g < 4; g++) {
            uint32_t pa[4];
            pa[0] = packh2(s[2 * g][0],     s[2 * g][1]);
            pa[1] = packh2(s[2 * g][2],     s[2 * g][3]);
            pa[2] = packh2(s[2 * g + 1][0], s[2 * g + 1][1]);
            pa[3] = packh2(s[2 * g + 1][2], s[2 * g + 1][3]);
#pragma unroll
            for (int nt = 0; nt < 16; nt++) {
                uint32_t bf[2];
                bf[0] = ld32h(VTst + (nt * 8 + r) * VTPH + g * 16 + 2 * q);
                bf[1] = ld32h(VTst + (nt * 8 + r) * VTPH + g * 16 + 8 + 2 * q);
                mma16816(of[nt], pa, bf);
            }
        }

        // ---- deferred row-sum reduction
        sA += __shfl_xor_sync(0xFFFFFFFFu, sA, 1);
        sA += __shfl_xor_sync(0xFFFFFFFFu, sA, 2);
        sB += __shfl_xor_sync(0xFFFFFFFFu, sB, 1);
        sB += __shfl_xor_sync(0xFFFFFFFFu, sB, 2);
        l0 = l0 * c0 + sA;
        l1 = l1 * c1 + sB;
    }

    // ---- epilogue: normalize + fp16 ctx
    float li0 = 1.f / l0, li1 = 1.f / l1;
    int growA = qt * FQ + rA, growB = qt * FQ + rB;
#pragma unroll
    for (int nt = 0; nt < 16; nt++) {
        int col = h * HD + nt * 8 + 2 * q;
        *(__half2*)&g_ctxh[(size_t)(b * SEQ + growA) * HID + col] =
            __floats2half2_rn(of[nt][0] * li0, of[nt][1] * li0);
        *(__half2*)&g_ctxh[(size_t)(b * SEQ + growB) * HID + col] =
            __floats2half2_rn(of[nt][2] * li1, of[nt][3] * li1);
    }
}

// ---------------- launch ----------------
extern "C" void kernel_launch(void* const* d_in, const int* in_sizes, int n_in,
                              void* d_out, int out_size)
{
    const float* x    = (const float*)d_in[0];   // [B,S,H]
    const float* qkvw = (const float*)d_in[1];   // [H, 3H]
    const float* dw   = (const float*)d_in[2];   // [H, H]
    const float* rel  = (const float*)d_in[3];   // [32, 16]
    float* out = (float*)d_out;

    __half *p_qkvh, *p_ctxh, *p_xh, *p_wqkvh, *p_dwh;
    cudaGetSymbolAddress((void**)&p_qkvh,  g_qkvh);
    cudaGetSymbolAddress((void**)&p_ctxh,  g_ctxh);
    cudaGetSymbolAddress((void**)&p_xh,    g_xh);
    cudaGetSymbolAddress((void**)&p_wqkvh, g_wqkvh);
    cudaGetSymbolAddress((void**)&p_dwh,   g_dwh);

    cudaFuncSetAttribute(gemm_h<__half>, cudaFuncAttributeMaxDynamicSharedMemorySize, GEMM_SMEM);
    cudaFuncSetAttribute(gemm_h<float>,  cudaFuncAttributeMaxDynamicSharedMemorySize, GEMM_SMEM);
    cudaFuncSetAttribute(flash_mma_kernel, cudaFuncAttributeMaxDynamicSharedMemorySize, FLASH_SMEM);

    // Launch order keeps QKV GEMM as the 4th launch (ncu capture slot).
    rope_table_kernel<<<(SEQ * 64) / 256, 256>>>();
    transpose_h_kernel<<<dim3(3 * HID / 32, HID / 32), 256>>>(qkvw, p_wqkvh, HID, 3 * HID);
    convert_h_kernel<<<(BATCH * SEQ * HID / 4) / 256, 256>>>(x, p_xh);
    // 4) QKV GEMM (fp16 mma)  <-- profiled launch
    gemm_h<__half><<<dim3(3 * HID / GBN, BATCH * SEQ / GBM), 256, GEMM_SMEM>>>(
        p_xh, p_wqkvh, p_qkvh, BATCH * SEQ, 3 * HID, HID);
    transpose_h_kernel<<<dim3(HID / 32, HID / 32), 256>>>(dw, p_dwh, HID, HID);
    rope_split_kernel<<<(BATCH * SEQ * NHEADS * 64) / 256, 256>>>();
    vtrans_kernel<<<dim3(SEQ / 32, HD / 32, BATCH * NHEADS), 256>>>();
    bias_kernel<<<(NHEADS * SEQ + 255) / 256, 256>>>(rel);
    flash_mma_kernel<<<dim3(SEQ / FQ, NHEADS, BATCH), 256, FLASH_SMEM>>>();
    // dense GEMM (fp16 in, fp32 out)
    gemm_h<float><<<dim3(HID / GBN, BATCH * SEQ / GBM), 256, GEMM_SMEM>>>(
        p_ctxh, p_dwh, out, BATCH * SEQ, HID, HID);
}

// round 11
// speedup vs baseline: 1.8800x; 1.1056x over previous
#include <cuda_runtime.h>
#include <cuda_fp16.h>
#include <math.h>
#include <float.h>
#include <stdint.h>

#define BATCH   2
#define SEQ     2048
#define HID     2048
#define NHEADS  16
#define HD      128

// ---------------- static scratch (no allocations allowed) ----------------
__device__ __half g_qkvh [BATCH * SEQ * 3 * HID];       // [B,S,3H] fp16 (QKV gemm out)
__device__ __half g_Qh   [BATCH * NHEADS * SEQ * HD];   // [B,NH,S,D]
__device__ __half g_Kh   [BATCH * NHEADS * SEQ * HD];
__device__ __half g_Vh   [BATCH * NHEADS * SEQ * HD];
__device__ __half g_VTh  [BATCH * NHEADS * HD * SEQ];   // [B,NH,D,S]
__device__ __half g_ctxh [BATCH * SEQ * HID];           // [B,S,H]
__device__ __half g_xh   [BATCH * SEQ * HID];           // fp16 x
__device__ __half g_wqkvh[3 * HID * HID];               // [3H,H]  qkv_w^T fp16
__device__ __half g_dwh  [HID * HID];                   // [H,H]   dense_w^T fp16
__device__ float  g_bias [NHEADS * SEQ];                // bias[h][q-k] * log2(e)
__device__ float  g_cos  [SEQ * 64];
__device__ float  g_sin  [SEQ * 64];

// ======================= helpers =======================
__device__ __forceinline__ uint32_t smem_u32(const void* p) {
    uint32_t a;
    asm("{ .reg .u64 t; cvta.to.shared.u64 t, %1; cvt.u32.u64 %0, t; }"
        : "=r"(a) : "l"(p));
    return a;
}
__device__ __forceinline__ void cp16(uint32_t s, const void* g) {
    asm volatile("cp.async.cg.shared.global [%0], [%1], 16;" :: "r"(s), "l"(g));
}
__device__ __forceinline__ void cp4(uint32_t s, const void* g) {
    asm volatile("cp.async.ca.shared.global [%0], [%1], 4;" :: "r"(s), "l"(g));
}
#define CP_COMMIT() asm volatile("cp.async.commit_group;" ::: "memory")
#define CP_WAIT2()  asm volatile("cp.async.wait_group 2;"  ::: "memory")
#define CP_WAIT1()  asm volatile("cp.async.wait_group 1;"  ::: "memory")
#define CP_WAIT0()  asm volatile("cp.async.wait_group 0;"  ::: "memory")

__device__ __forceinline__ uint32_t packh2(float x, float y) {
    __half2 h = __floats2half2_rn(x, y);
    return *(uint32_t*)&h;
}

// ldmatrix x4: loads 4 8x8 f16 matrices; lanes 0-7/8-15/16-23/24-31 give row addrs.
__device__ __forceinline__ void ldm_x4(uint32_t* r, uint32_t addr) {
    asm volatile("ldmatrix.sync.aligned.m8n8.x4.shared.b16 {%0,%1,%2,%3}, [%4];"
        : "=r"(r[0]), "=r"(r[1]), "=r"(r[2]), "=r"(r[3]) : "r"(addr));
}

// fp16 mma: D(f32) += A(f16 m16k16, row) * B(f16 k16n8, col)
__device__ __forceinline__ void mma16816(float* d, const uint32_t* a, const uint32_t* b) {
    asm volatile(
        "mma.sync.aligned.m16n8k16.row.col.f32.f16.f16.f32 "
        "{%0,%1,%2,%3}, {%4,%5,%6,%7}, {%8,%9}, {%0,%1,%2,%3};"
        : "+f"(d[0]), "+f"(d[1]), "+f"(d[2]), "+f"(d[3])
        : "r"(a[0]), "r"(a[1]), "r"(a[2]), "r"(a[3]), "r"(b[0]), "r"(b[1]));
}

// ======================= f32 -> f16 convert (elementwise) =======================
__global__ __launch_bounds__(256) void convert_h_kernel(
    const float* __restrict__ in, __half* __restrict__ out)
{
    int i = blockIdx.x * blockDim.x + threadIdx.x;
    float4 v = ((const float4*)in)[i];
    __half2* o = (__half2*)out;
    o[2 * i]     = __floats2half2_rn(v.x, v.y);
    o[2 * i + 1] = __floats2half2_rn(v.z, v.w);
}

// ======================= f32 [R][C] -> f16 [C][R] transpose =======================
__global__ __launch_bounds__(256) void transpose_h_kernel(
    const float* __restrict__ in, __half* __restrict__ out, int R, int C)
{
    __shared__ float t[32][33];
    int bx = blockIdx.x * 32, by = blockIdx.y * 32;
    int tx = threadIdx.x & 31, ty = threadIdx.x >> 5;
#pragma unroll
    for (int i = 0; i < 32; i += 8)
        t[ty + i][tx] = in[(size_t)(by + ty + i) * C + bx + tx];
    __syncthreads();
#pragma unroll
    for (int i = 0; i < 32; i += 8)
        out[(size_t)(bx + ty + i) * R + by + tx] = __float2half_rn(t[tx][ty + i]);
}

// ======================= RoPE cos/sin table =======================
__global__ __launch_bounds__(256) void rope_table_kernel()
{
    int idx = blockIdx.x * blockDim.x + threadIdx.x;   // SEQ*64
    int s = idx >> 6, d = idx & 63;
    float inv = powf(10000.f, -(float)d * (1.f / 64.f));
    float sn, cs;
    sincosf((float)s * inv, &sn, &cs);
    g_cos[idx] = cs;
    g_sin[idx] = sn;
}

// ======================= fp16 mma GEMM: C[M,N] = A[M,K] @ Bt[N,K]^T ================
// 128x128 C-tile, chunk = 32 k-halves (2 k16 steps), 4 stages, occ 2, ldmatrix frags.
#define GBM 128
#define GBN 128
#define GBKH 32                      // k halves per chunk
#define GPITCH 40                    // halves; 80B rows -> conflict-free ldmatrix
#define STG_HALFS (2 * 128 * GPITCH) // A + B = 10240 halves = 20480 B
#define GEMM_SMEM (4 * STG_HALFS * 2)   // 81920 B -> 2 CTAs/SM

template <typename OutT>
__global__ __launch_bounds__(256, 2) void gemm_h(
    const __half* __restrict__ A, const __half* __restrict__ Bt,
    OutT* __restrict__ C, int M, int N, int K)
{
    extern __shared__ __half smh[];
    const int tid  = threadIdx.x;
    const int warp = tid >> 5, lane = tid & 31;
    const int wm = (warp >> 2) * 64;
    const int wn = (warp & 3) * 32;
    const int r  = lane >> 2;
    const int q  = lane & 3;
    const int row0 = blockIdx.y * GBM;
    const int col0 = blockIdx.x * GBN;
    const uint32_t sb = smem_u32(smh);
    const int NC = K / GBKH;

    // ldmatrix per-lane offsets (halves)
    const int aOff = (wm + (lane & 15)) * GPITCH + ((lane >> 4) & 1) * 8;
    const int bOff = (wn + (lane & 7) + ((lane >> 4) & 1) * 8) * GPITCH
                   + ((lane >> 3) & 1) * 8;

    float cf[4][4][4];
#pragma unroll
    for (int i = 0; i < 4; i++)
#pragma unroll
        for (int j = 0; j < 4; j++)
#pragma unroll
            for (int t = 0; t < 4; t++) cf[i][j][t] = 0.f;

    const int lrow = tid >> 1;              // 0..127
    const int lseg = (tid & 1) * 2;         // 0 or 2 (16-byte segs of 8 halves)

    auto load_stage = [&](int c, int s) {
        uint32_t base = sb + (uint32_t)(s * STG_HALFS) * 2u;
#pragma unroll
        for (int j = 0; j < 2; j++) {
            int seg = lseg + j;
            cp16(base + (uint32_t)(lrow * GPITCH + seg * 8) * 2u,
                 A + (size_t)(row0 + lrow) * K + c * GBKH + seg * 8);
            cp16(base + (uint32_t)(128 * GPITCH + lrow * GPITCH + seg * 8) * 2u,
                 Bt + (size_t)(col0 + lrow) * K + c * GBKH + seg * 8);
        }
        CP_COMMIT();
    };

    load_stage(0, 0);
    load_stage(1, 1);
    load_stage(2, 2);

    for (int c = 0; c < NC; ++c) {
        CP_WAIT2();
        __syncthreads();
        int nc = c + 3;
        if (nc < NC) load_stage(nc, nc & 3); else CP_COMMIT();

        uint32_t aBase = sb + (uint32_t)((c & 3) * STG_HALFS) * 2u;
        uint32_t bBase = aBase + (uint32_t)(128 * GPITCH) * 2u;
#pragma unroll
        for (int step = 0; step < 2; step++) {
            const int kk = step * 16;
            uint32_t af[4][4], bt[2][4];
#pragma unroll
            for (int mt = 0; mt < 4; mt++)
                ldm_x4(af[mt], aBase + (uint32_t)(aOff + mt * 16 * GPITCH + kk) * 2u);
#pragma unroll
            for (int p = 0; p < 2; p++)
                ldm_x4(bt[p], bBase + (uint32_t)(bOff + p * 16 * GPITCH + kk) * 2u);
#pragma unroll
            for (int mt = 0; mt < 4; mt++) {
                mma16816(cf[mt][0], af[mt], &bt[0][0]);
                mma16816(cf[mt][1], af[mt], &bt[0][2]);
                mma16816(cf[mt][2], af[mt], &bt[1][0]);
                mma16816(cf[mt][3], af[mt], &bt[1][2]);
            }
        }
    }

#pragma unroll
    for (int mt = 0; mt < 4; mt++) {
        int row = row0 + wm + mt * 16 + r;
#pragma unroll
        for (int nt = 0; nt < 4; nt++) {
            int col = col0 + wn + nt * 8 + 2 * q;
            if (sizeof(OutT) == 2) {
                *(__half2*)((__half*)C + (size_t)row * N + col) =
                    __floats2half2_rn(cf[mt][nt][0], cf[mt][nt][1]);
                *(__half2*)((__half*)C + (size_t)(row + 8) * N + col) =
                    __floats2half2_rn(cf[mt][nt][2], cf[mt][nt][3]);
            } else {
                *(float2*)((float*)C + (size_t)row * N + col) =
                    make_float2(cf[mt][nt][0], cf[mt][nt][1]);
                *(float2*)((float*)C + (size_t)(row + 8) * N + col) =
                    make_float2(cf[mt][nt][2], cf[mt][nt][3]);
            }
        }
    }
}

// ---------------- RoPE + split (fp16 in/out) ----------------
__global__ __launch_bounds__(256) void rope_split_kernel()
{
    int t = blockIdx.x * blockDim.x + threadIdx.x;
    int d = t & 63;
    int h = (t >> 6) & (NHEADS - 1);
    int s = (t >> 10) & (SEQ - 1);
    int b = t >> 21;

    const __half* base = g_qkvh + ((size_t)(b * SEQ + s)) * (3 * HID) + h * HD;
    float q1 = __half2float(base[d]),            q2 = __half2float(base[d + 64]);
    float k1 = __half2float(base[HID + d]),      k2 = __half2float(base[HID + d + 64]);
    float v1 = __half2float(base[2 * HID + d]),  v2 = __half2float(base[2 * HID + d + 64]);

    float cs = g_cos[s * 64 + d];
    float sn = g_sin[s * 64 + d];

    size_t o = ((size_t)((b * NHEADS + h) * SEQ + s)) * HD;
    g_Qh[o + d]      = __float2half_rn(q1 * cs - q2 * sn);
    g_Qh[o + d + 64] = __float2half_rn(q2 * cs + q1 * sn);
    g_Kh[o + d]      = __float2half_rn(k1 * cs - k2 * sn);
    g_Kh[o + d + 64] = __float2half_rn(k2 * cs + k1 * sn);
    g_Vh[o + d]      = __float2half_rn(v1);
    g_Vh[o + d + 64] = __float2half_rn(v2);
}

// ---------------- V transpose: [B,NH,S,D] -> [B,NH,D,S] ----------------
__global__ __launch_bounds__(256) void vtrans_kernel()
{
    __shared__ __half t[32][33];
    int s0 = blockIdx.x * 32, d0 = blockIdx.y * 32;
    size_t base = (size_t)blockIdx.z * SEQ * HD;
    int tx = threadIdx.x & 31, ty = threadIdx.x >> 5;
#pragma unroll
    for (int i = 0; i < 32; i += 8)
        t[ty + i][tx] = g_Vh[base + (size_t)(s0 + ty + i) * HD + d0 + tx];
    __syncthreads();
#pragma unroll
    for (int i = 0; i < 32; i += 8)
        g_VTh[base + (size_t)(d0 + ty + i) * SEQ + s0 + tx] = t[tx][ty + i];
}

// ---------------- relative-position bias table (pre-scaled by log2 e) ----------------
__global__ void bias_kernel(const float* __restrict__ rel)
{
    int idx = blockIdx.x * blockDim.x + threadIdx.x;
    if (idx >= NHEADS * SEQ) return;
    int h = idx >> 11;
    int n = idx & (SEQ - 1);
    int bucket;
    if (n < 16) {
        bucket = n;
    } else {
        float val = logf((float)n * (1.f / 16.f)) / logf(8.f) * 16.f;
        int bi = (int)val + 16;
        bucket = bi < 31 ? bi : 31;
    }
    g_bias[idx] = rel[bucket * NHEADS + h] * 1.4426950408889634f;
}

// ---------------- flash attention, fp16 mma + ldmatrix ----------------
// 128 q-rows per block, 64 k-cols per iter. Q/K [row][d] pitch 136; VT [d][key] pitch 72.
#define FQ   128
#define FKC  64
#define QPH  136
#define VTPH 72
#define OFF_KH  (FQ * QPH)                 // 17408 halves
#define OFF_VTH (OFF_KH + 2 * FKC * QPH)   // 34816 halves
#define OFF_BB  ((OFF_VTH + 2 * HD * VTPH) * 2)   // byte offset of bias floats
#define FLASH_SMEM (OFF_BB + 2 * 192 * 4)

__global__ __launch_bounds__(256, 1) void flash_mma_kernel()
{
    extern __shared__ __half smh[];
    float* biasb = (float*)((char*)smh + OFF_BB);

    const int qt = (int)gridDim.x - 1 - (int)blockIdx.x;   // heavy blocks first
    const int h = blockIdx.y, b = blockIdx.z;
    const int tid  = threadIdx.x;
    const int warp = tid >> 5, lane = tid & 31;
    const int r = lane >> 2, q = lane & 3;
    const int wr0 = warp * 16;
    const int rA = wr0 + r, rB = rA + 8;
    const uint32_t sbase = smem_u32(smh);

    // ldmatrix per-lane offsets (halves)
    const int qOff = (wr0 + (lane & 15)) * QPH + ((lane >> 4) & 1) * 8;
    const int kOff = ((lane & 7) + ((lane >> 4) & 1) * 8) * QPH + ((lane >> 3) & 1) * 8;
    const int vOff = ((lane & 7) + ((lane >> 4) & 1) * 8) * VTPH + ((lane >> 3) & 1) * 8;

    const size_t headBase = (size_t)(b * NHEADS + h) * SEQ * HD;
    const __half* Qg  = g_Qh + headBase + (size_t)qt * FQ * HD;
    const __half* VTg = g_VTh + headBase;
    const float* biasH = g_bias + h * SEQ;

    const float SCL2 = 0.08838834764831845f * 1.4426950408889634f;

    // prolog: Q (group0), then K/VT tile 0 + bias0 (group1)
#pragma unroll
    for (int i = 0; i < 8; i++) {
        int f = tid + i * 256; int rr = f >> 4, c16 = f & 15;
        cp16(sbase + (uint32_t)(rr * QPH + c16 * 8) * 2u, Qg + rr * HD + c16 * 8);
    }
    CP_COMMIT();
    {
        const __half* Kg = g_Kh + headBase;
#pragma unroll
        for (int i = 0; i < 4; i++) {
            int f = tid + i * 256;
            int rr = f >> 4, c16 = f & 15;
            cp16(sbase + (uint32_t)(OFF_KH + rr * QPH + c16 * 8) * 2u, Kg + rr * HD + c16 * 8);
            int vr = f >> 3, c8 = f & 7;
            cp16(sbase + (uint32_t)(OFF_VTH + vr * VTPH + c8 * 8) * 2u, VTg + (size_t)vr * SEQ + c8 * 8);
        }
        if (tid < 192) {
            int dl = qt * FQ + tid - 63;
            cp4(sbase + (uint32_t)OFF_BB + tid * 4u, biasH + (dl >= 0 ? dl : 0));
        }
        CP_COMMIT();
    }
    CP_WAIT1();                        // Q resident
    __syncthreads();

    // hoist Q fragments via ldmatrix (8 k16 steps)
    uint32_t qf[8][4];
#pragma unroll
    for (int g = 0; g < 8; g++)
        ldm_x4(qf[g], sbase + (uint32_t)(qOff + g * 16) * 2u);

    float m0 = -1e30f, m1 = -1e30f, l0 = 0.f, l1 = 0.f;
    float of[16][4];
#pragma unroll
    for (int nt = 0; nt < 16; nt++)
#pragma unroll
        for (int e = 0; e < 4; e++) of[nt][e] = 0.f;

    const int NT = 2 * qt + 2;

    for (int kt = 0; kt < NT; ++kt) {
        __syncthreads();
        if (kt + 1 < NT) {
            const int ns = (kt + 1) & 1;
            const __half* Kg = g_Kh + headBase + (size_t)(kt + 1) * FKC * HD;
            const int keyb = (kt + 1) * FKC;
#pragma unroll
            for (int i = 0; i < 4; i++) {
                int f = tid + i * 256;
                int rr = f >> 4, c16 = f & 15;
                cp16(sbase + (uint32_t)(OFF_KH + ns * FKC * QPH + rr * QPH + c16 * 8) * 2u,
                     Kg + rr * HD + c16 * 8);
                int vr = f >> 3, c8 = f & 7;
                cp16(sbase + (uint32_t)(OFF_VTH + ns * HD * VTPH + vr * VTPH + c8 * 8) * 2u,
                     VTg + (size_t)vr * SEQ + keyb + c8 * 8);
            }
            if (tid < 192) {
                int dl = qt * FQ - (kt + 1) * FKC + tid - 63;
                cp4(sbase + (uint32_t)OFF_BB + (ns * 192 + tid) * 4u,
                    biasH + (dl >= 0 ? dl : 0));
            }
            CP_COMMIT();
            CP_WAIT1();
        } else {
            CP_WAIT0();
        }
        __syncthreads();

        const int base = qt * FQ - kt * FKC;
        if (base < -(wr0 + 15)) continue;       // fully-masked warp

        uint32_t kBase = sbase + (uint32_t)(OFF_KH  + (kt & 1) * FKC * QPH) * 2u;
        uint32_t vBase = sbase + (uint32_t)(OFF_VTH + (kt & 1) * HD * VTPH) * 2u;
        const float* bsm = biasb + (kt & 1) * 192;

        // ---- S = Q K^T (16 x 64 per warp): ldmatrix b-frag pairs
        float s[8][4];
#pragma unroll
        for (int nt = 0; nt < 8; nt++)
#pragma unroll
            for (int e = 0; e < 4; e++) s[nt][e] = 0.f;

#pragma unroll
        for (int g = 0; g < 8; g++) {
#pragma unroll
            for (int p = 0; p < 4; p++) {
                uint32_t bt[4];
                ldm_x4(bt, kBase + (uint32_t)(kOff + p * 16 * QPH + g * 16) * 2u);
                mma16816(s[2 * p],     qf[g], &bt[0]);
                mma16816(s[2 * p + 1], qf[g], &bt[2]);
            }
        }

        // ---- scale + bias + causal mask
        const bool dg = (base < FQ);
#pragma unroll
        for (int nt = 0; nt < 8; nt++) {
            int lc = nt * 8 + 2 * q;
            float v0 = s[nt][0] * SCL2 + bsm[rA - lc + 63];
            float v1 = s[nt][1] * SCL2 + bsm[rA - lc + 62];
            float v2 = s[nt][2] * SCL2 + bsm[rB - lc + 63];
            float v3 = s[nt][3] * SCL2 + bsm[rB - lc + 62];
            s[nt][0] = (dg && lc     > rA + base) ? -1e30f : v0;
            s[nt][1] = (dg && lc + 1 > rA + base) ? -1e30f : v1;
            s[nt][2] = (dg && lc     > rB + base) ? -1e30f : v2;
            s[nt][3] = (dg && lc + 1 > rB + base) ? -1e30f : v3;
        }

        // ---- row max within quad
        float mxA = -1e30f, mxB = -1e30f;
#pragma unroll
        for (int nt = 0; nt < 8; nt++) {
            mxA = fmaxf(mxA, fmaxf(s[nt][0], s[nt][1]));
            mxB = fmaxf(mxB, fmaxf(s[nt][2], s[nt][3]));
        }
        mxA = fmaxf(mxA, __shfl_xor_sync(0xFFFFFFFFu, mxA, 1));
        mxA = fmaxf(mxA, __shfl_xor_sync(0xFFFFFFFFu, mxA, 2));
        mxB = fmaxf(mxB, __shfl_xor_sync(0xFFFFFFFFu, mxB, 1));
        mxB = fmaxf(mxB, __shfl_xor_sync(0xFFFFFFFFu, mxB, 2));
        float mn0 = fmaxf(m0, mxA), mn1 = fmaxf(m1, mxB);
        float c0 = exp2f(m0 - mn0), c1 = exp2f(m1 - mn1);
        m0 = mn0; m1 = mn1;

        // ---- P = exp2(s - m); partial sums
        float sA = 0.f, sB = 0.f;
#pragma unroll
        for (int nt = 0; nt < 8; nt++) {
            s[nt][0] = exp2f(s[nt][0] - mn0);
            s[nt][1] = exp2f(s[nt][1] - mn0);
            s[nt][2] = exp2f(s[nt][2] - mn1);
            s[nt][3] = exp2f(s[nt][3] - mn1);
            sA += s[nt][0] + s[nt][1];
            sB += s[nt][2] + s[nt][3];
        }

        // ---- rescale O
#pragma unroll
        for (int nt = 0; nt < 16; nt++) {
            of[nt][0] *= c0; of[nt][1] *= c0;
            of[nt][2] *= c1; of[nt][3] *= c1;
        }

        // ---- O += P V : P already in A-frag layout; VT b-frags via ldmatrix
#pragma unroll
        for (int g = 0; g < 4; g++) {
            uint32_t pa[4];
            pa[0] = packh2(s[2 * g][0],     s[2 * g][1]);
            pa[1] = packh2(s[2 * g][2],     s[2 * g][3]);
            pa[2] = packh2(s[2 * g + 1][0], s[2 * g + 1][1]);
            pa[3] = packh2(s[2 * g + 1][2], s[2 * g + 1][3]);
#pragma unroll
            for (int p = 0; p < 8; p++) {
                uint32_t bt[4];
                ldm_x4(bt, vBase + (uint32_t)(vOff + p * 16 * VTPH + g * 16) * 2u);
                mma16816(of[2 * p],     pa, &bt[0]);
                mma16816(of[2 * p + 1], pa, &bt[2]);
            }
        }

        // ---- deferred row-sum reduction
        sA += __shfl_xor_sync(0xFFFFFFFFu, sA, 1);
        sA += __shfl_xor_sync(0xFFFFFFFFu, sA, 2);
        sB += __shfl_xor_sync(0xFFFFFFFFu, sB, 1);
        sB += __shfl_xor_sync(0xFFFFFFFFu, sB, 2);
        l0 = l0 * c0 + sA;
        l1 = l1 * c1 + sB;
    }

    // ---- epilogue: normalize + fp16 ctx
    float li0 = 1.f / l0, li1 = 1.f / l1;
    int growA = qt * FQ + rA, growB = qt * FQ + rB;
#pragma unroll
    for (int nt = 0; nt < 16; nt++) {
        int col = h * HD + nt * 8 + 2 * q;
        *(__half2*)&g_ctxh[(size_t)(b * SEQ + growA) * HID + col] =
            __floats2half2_rn(of[nt][0] * li0, of[nt][1] * li0);
        *(__half2*)&g_ctxh[(size_t)(b * SEQ + growB) * HID + col] =
            __floats2half2_rn(of[nt][2] * li1, of[nt][3] * li1);
    }
}

// ---------------- launch ----------------
extern "C" void kernel_launch(void* const* d_in, const int* in_sizes, int n_in,
                              void* d_out, int out_size)
{
    const float* x    = (const float*)d_in[0];   // [B,S,H]
    const float* qkvw = (const float*)d_in[1];   // [H, 3H]
    const float* dw   = (const float*)d_in[2];   // [H, H]
    const float* rel  = (const float*)d_in[3];   // [32, 16]
    float* out = (float*)d_out;

    __half *p_qkvh, *p_ctxh, *p_xh, *p_wqkvh, *p_dwh;
    cudaGetSymbolAddress((void**)&p_qkvh,  g_qkvh);
    cudaGetSymbolAddress((void**)&p_ctxh,  g_ctxh);
    cudaGetSymbolAddress((void**)&p_xh,    g_xh);
    cudaGetSymbolAddress((void**)&p_wqkvh, g_wqkvh);
    cudaGetSymbolAddress((void**)&p_dwh,   g_dwh);

    cudaFuncSetAttribute(gemm_h<__half>, cudaFuncAttributeMaxDynamicSharedMemorySize, GEMM_SMEM);
    cudaFuncSetAttribute(gemm_h<float>,  cudaFuncAttributeMaxDynamicSharedMemorySize, GEMM_SMEM);
    cudaFuncSetAttribute(flash_mma_kernel, cudaFuncAttributeMaxDynamicSharedMemorySize, FLASH_SMEM);

    // Launch order keeps QKV GEMM as the 4th launch (ncu capture slot).
    rope_table_kernel<<<(SEQ * 64) / 256, 256>>>();
    transpose_h_kernel<<<dim3(3 * HID / 32, HID / 32), 256>>>(qkvw, p_wqkvh, HID, 3 * HID);
    convert_h_kernel<<<(BATCH * SEQ * HID / 4) / 256, 256>>>(x, p_xh);
    // 4) QKV GEMM (fp16 mma + ldmatrix)  <-- profiled launch
    gemm_h<__half><<<dim3(3 * HID / GBN, BATCH * SEQ / GBM), 256, GEMM_SMEM>>>(
        p_xh, p_wqkvh, p_qkvh, BATCH * SEQ, 3 * HID, HID);
    transpose_h_kernel<<<dim3(HID / 32, HID / 32), 256>>>(dw, p_dwh, HID, HID);
    rope_split_kernel<<<(BATCH * SEQ * NHEADS * 64) / 256, 256>>>();
    vtrans_kernel<<<dim3(SEQ / 32, HD / 32, BATCH * NHEADS), 256>>>();
    bias_kernel<<<(NHEADS * SEQ + 255) / 256, 256>>>(rel);
    flash_mma_kernel<<<dim3(SEQ / FQ, NHEADS, BATCH), 256, FLASH_SMEM>>>();
    // dense GEMM (fp16 in, fp32 out)
    gemm_h<float><<<dim3(HID / GBN, BATCH * SEQ / GBM), 256, GEMM_SMEM>>>(
        p_ctxh, p_dwh, out, BATCH * SEQ, HID, HID);
}